// round 3
// baseline (speedup 1.0000x reference)
#include <cuda_runtime.h>
#include <cstdint>
#include <cstddef>

#define NN 100000
#define NE 1600000
#define DD 128

// Scratch (static device globals; no allocation allowed)
__device__ float g_agg[(size_t)NN * DD];   // 51.2 MB
__device__ float g_h[(size_t)NN * DD];     // 51.2 MB
__device__ float g_deg[NN];
__device__ int   g_is64;

// ---------------------------------------------------------------------------
// Detect whether edge_index is int64 or int32.
// If int64 (little-endian, values < 2^32), every odd 32-bit word is 0.
// If int32, odd words are random node ids — probability all 8192 are zero ~ 0.
// ---------------------------------------------------------------------------
__global__ void detect_kernel(const unsigned int* __restrict__ ebuf) {
    __shared__ int nz;
    if (threadIdx.x == 0) nz = 0;
    __syncthreads();
    for (int i = threadIdx.x; i < 8192; i += blockDim.x) {
        if (ebuf[2 * i + 1] != 0u) nz = 1;
    }
    __syncthreads();
    if (threadIdx.x == 0) g_is64 = (nz == 0) ? 1 : 0;
}

// ---------------------------------------------------------------------------
// Vectorized zero fill
// ---------------------------------------------------------------------------
__global__ void zero_kernel(float4* __restrict__ p, int n4) {
    int i = blockIdx.x * blockDim.x + threadIdx.x;
    const int stride = gridDim.x * blockDim.x;
    const float4 z = make_float4(0.f, 0.f, 0.f, 0.f);
    for (; i < n4; i += stride) p[i] = z;
}

// ---------------------------------------------------------------------------
// Edge scatter: warp per edge.  agg[dst] += x[src]; deg[dst] += 1 (layer 1).
// Each lane handles 4 floats (float4 gather + red.global.add.v4.f32 scatter).
// ---------------------------------------------------------------------------
__global__ void scatter_kernel(const float4* __restrict__ xin,
                               const void* __restrict__ edges,
                               float* __restrict__ agg,
                               float* __restrict__ deg)
{
    const int lane = threadIdx.x & 31;
    int w = (blockIdx.x * blockDim.x + threadIdx.x) >> 5;
    const int nw = (gridDim.x * blockDim.x) >> 5;
    const int is64 = g_is64;
    const long long* e64 = (const long long*)edges;
    const int*       e32 = (const int*)edges;

    for (int e = w; e < NE; e += nw) {
        int src, dst;
        if (is64) { src = (int)e64[e]; dst = (int)e64[NE + e]; }
        else      { src = e32[e];      dst = e32[NE + e]; }

        float4 v = __ldg(&xin[(size_t)src * (DD / 4) + lane]);
        float* a = agg + (size_t)dst * DD + lane * 4;
        asm volatile("red.global.add.v4.f32 [%0], {%1,%2,%3,%4};"
                     :: "l"(a), "f"(v.x), "f"(v.y), "f"(v.z), "f"(v.w)
                     : "memory");
        if (deg != nullptr && lane == 0) {
            atomicAdd(deg + dst, 1.0f);
        }
    }
}

// ---------------------------------------------------------------------------
// Node update:  out = (agg * inv_deg) @ Wl^T + bias + xr @ Wr^T  [+ relu]
// Fused SGEMM: M=NN, N=128, K=256 (two 128-halves).  BM=128, BN=128, BK=16,
// 256 threads, 8x8 microtile per thread.
// ---------------------------------------------------------------------------
__global__ __launch_bounds__(256, 2)
void node_kernel(const float* __restrict__ agg,
                 const float* __restrict__ xr,
                 const float* __restrict__ deg,
                 const float* __restrict__ Wl,   // [128][128] row-major: W[j][k]
                 const float* __restrict__ Wr,
                 const float* __restrict__ bias,
                 float* __restrict__ out,
                 int do_relu)
{
    __shared__ float As[16][132];   // [k][row], padded
    __shared__ float Bs[16][132];   // [k][col], padded

    const int t    = threadIdx.x;
    const int trow = t >> 4;          // 0..15  (C microtile row group)
    const int tcol = t & 15;          // 0..15  (C microtile col group)
    const int lrow = t & 127;         // load row / weight row
    const int koff = (t >> 7) << 3;   // 0 or 8
    const int row0 = blockIdx.x << 7;
    const int grow = row0 + lrow;
    const bool rv  = grow < NN;

    float inv = 0.f;
    if (rv) inv = 1.0f / fmaxf(deg[grow], 1.0f);

    float acc[8][8];
#pragma unroll
    for (int i = 0; i < 8; ++i)
#pragma unroll
        for (int j = 0; j < 8; ++j) acc[i][j] = 0.f;

#pragma unroll
    for (int half = 0; half < 2; ++half) {
        const float* Asrc  = half ? xr : agg;
        const float* Wsrc  = half ? Wr : Wl;
        const float  scale = half ? 1.0f : inv;

#pragma unroll 1
        for (int k0 = 0; k0 < 128; k0 += 16) {
            // ---- load A tile (transposed into smem, scaled) ----
            float4 v0 = make_float4(0.f, 0.f, 0.f, 0.f), v1 = v0;
            if (rv) {
                const float4* p = (const float4*)(Asrc + (size_t)grow * DD + k0 + koff);
                v0 = p[0];
                v1 = p[1];
            }
            As[koff + 0][lrow] = v0.x * scale;
            As[koff + 1][lrow] = v0.y * scale;
            As[koff + 2][lrow] = v0.z * scale;
            As[koff + 3][lrow] = v0.w * scale;
            As[koff + 4][lrow] = v1.x * scale;
            As[koff + 5][lrow] = v1.y * scale;
            As[koff + 6][lrow] = v1.z * scale;
            As[koff + 7][lrow] = v1.w * scale;

            // ---- load B tile = W^T (transposed into smem) ----
            const float4* q = (const float4*)(Wsrc + (size_t)lrow * DD + k0 + koff);
            float4 w0 = q[0];
            float4 w1 = q[1];
            Bs[koff + 0][lrow] = w0.x;
            Bs[koff + 1][lrow] = w0.y;
            Bs[koff + 2][lrow] = w0.z;
            Bs[koff + 3][lrow] = w0.w;
            Bs[koff + 4][lrow] = w1.x;
            Bs[koff + 5][lrow] = w1.y;
            Bs[koff + 6][lrow] = w1.z;
            Bs[koff + 7][lrow] = w1.w;

            __syncthreads();

#pragma unroll
            for (int kk = 0; kk < 16; ++kk) {
                float a[8], b[8];
                *(float4*)&a[0] = *(const float4*)&As[kk][(trow << 3) + 0];
                *(float4*)&a[4] = *(const float4*)&As[kk][(trow << 3) + 4];
                *(float4*)&b[0] = *(const float4*)&Bs[kk][(tcol << 3) + 0];
                *(float4*)&b[4] = *(const float4*)&Bs[kk][(tcol << 3) + 4];
#pragma unroll
                for (int i = 0; i < 8; ++i)
#pragma unroll
                    for (int j = 0; j < 8; ++j)
                        acc[i][j] = fmaf(a[i], b[j], acc[i][j]);
            }
            __syncthreads();
        }
    }

    // ---- epilogue: bias (+relu), vectorized stores ----
    float bv[8];
#pragma unroll
    for (int j = 0; j < 8; ++j) bv[j] = bias[(tcol << 3) + j];

#pragma unroll
    for (int i = 0; i < 8; ++i) {
        const int r = row0 + (trow << 3) + i;
        if (r < NN) {
            float o[8];
#pragma unroll
            for (int j = 0; j < 8; ++j) {
                float v = acc[i][j] + bv[j];
                if (do_relu) v = fmaxf(v, 0.f);
                o[j] = v;
            }
            float* op = out + (size_t)r * DD + (tcol << 3);
            *(float4*)(op + 0) = *(float4*)&o[0];
            *(float4*)(op + 4) = *(float4*)&o[4];
        }
    }
}

// ---------------------------------------------------------------------------
// Launch sequence (default stream, graph-capturable, allocation-free)
// ---------------------------------------------------------------------------
extern "C" void kernel_launch(void* const* d_in, const int* in_sizes, int n_in,
                              void* d_out, int out_size)
{
    const float* x   = (const float*)d_in[0];
    const void*  ei  = d_in[1];
    const float* W1l = (const float*)d_in[2];
    const float* b1  = (const float*)d_in[3];
    const float* W1r = (const float*)d_in[4];
    const float* W2l = (const float*)d_in[5];
    const float* b2  = (const float*)d_in[6];
    const float* W2r = (const float*)d_in[7];
    float* out = (float*)d_out;

    float *agg, *h, *deg;
    cudaGetSymbolAddress((void**)&agg, g_agg);
    cudaGetSymbolAddress((void**)&h,   g_h);
    cudaGetSymbolAddress((void**)&deg, g_deg);

    detect_kernel<<<1, 256>>>((const unsigned int*)ei);

    // Layer 1
    zero_kernel<<<2048, 256>>>((float4*)agg, NN * DD / 4);
    zero_kernel<<<64, 256>>>((float4*)deg, NN / 4);
    scatter_kernel<<<4096, 256>>>((const float4*)x, ei, agg, deg);
    node_kernel<<<(NN + 127) / 128, 256>>>(agg, x, deg, W1l, W1r, b1, h, 1);

    // Layer 2 (degree reused)
    zero_kernel<<<2048, 256>>>((float4*)agg, NN * DD / 4);
    scatter_kernel<<<4096, 256>>>((const float4*)h, ei, agg, nullptr);
    node_kernel<<<(NN + 127) / 128, 256>>>(agg, h, deg, W2l, W2r, b2, out, 0);
}

// round 6
// speedup vs baseline: 1.2781x; 1.2781x over previous
#include <cuda_runtime.h>
#include <cstdint>
#include <cstddef>

#define NN 100000
#define NE 1600000
#define DD 128
#define NB_SCAN 98   // ceil(100000 / 1024)

// Scratch (static device globals; no allocation allowed)
__device__ float g_agg[(size_t)NN * DD];   // 51.2 MB
__device__ float g_h[(size_t)NN * DD];     // 51.2 MB
__device__ int   g_srcs[NE];               // CSR: src ids grouped by dst
__device__ int   g_rp[NN + 1];             // CSR row pointers
__device__ int   g_pos[NN];                // fill cursors
__device__ int   g_cnt[NN];                // degree histogram
__device__ int   g_bs[128];                // scan block sums
__device__ int   g_is64;

// ---------------------------------------------------------------------------
// Detect whether edge_index is int64 or int32 (odd 32-bit words all zero
// iff little-endian int64 with values < 2^32).
// ---------------------------------------------------------------------------
__global__ void detect_kernel(const unsigned int* __restrict__ ebuf) {
    __shared__ int nz;
    if (threadIdx.x == 0) nz = 0;
    __syncthreads();
    for (int i = threadIdx.x; i < 8192; i += blockDim.x) {
        if (ebuf[2 * i + 1] != 0u) nz = 1;
    }
    __syncthreads();
    if (threadIdx.x == 0) g_is64 = (nz == 0) ? 1 : 0;
}

__global__ void zero_int_kernel(int4* __restrict__ p, int n4) {
    int i = blockIdx.x * blockDim.x + threadIdx.x;
    const int stride = gridDim.x * blockDim.x;
    const int4 z = make_int4(0, 0, 0, 0);
    for (; i < n4; i += stride) p[i] = z;
}

// ---------------------------------------------------------------------------
// CSR build: histogram -> 3-pass exclusive scan -> fill
// ---------------------------------------------------------------------------
__global__ void hist_kernel(const void* __restrict__ edges,
                            int* __restrict__ cnt) {
    const int is64 = g_is64;
    const long long* e64 = (const long long*)edges;
    const int*       e32 = (const int*)edges;
    int i = blockIdx.x * blockDim.x + threadIdx.x;
    const int stride = gridDim.x * blockDim.x;
    for (; i < NE; i += stride) {
        int dst = is64 ? (int)e64[NE + i] : e32[NE + i];
        atomicAdd(&cnt[dst], 1);
    }
}

// Block scan: 1024 elements / block (256 threads x 4)
__global__ void scan1_kernel(const int* __restrict__ cnt,
                             int* __restrict__ rp,
                             int* __restrict__ bs) {
    __shared__ int wsum[8];
    const int t = threadIdx.x, lane = t & 31, w = t >> 5;
    const int base = blockIdx.x * 1024 + t * 4;
    int v0 = (base + 0 < NN) ? cnt[base + 0] : 0;
    int v1 = (base + 1 < NN) ? cnt[base + 1] : 0;
    int v2 = (base + 2 < NN) ? cnt[base + 2] : 0;
    int v3 = (base + 3 < NN) ? cnt[base + 3] : 0;
    const int tot = v0 + v1 + v2 + v3;
    int inc = tot;
#pragma unroll
    for (int off = 1; off < 32; off <<= 1) {
        int n = __shfl_up_sync(0xffffffff, inc, off);
        if (lane >= off) inc += n;
    }
    if (lane == 31) wsum[w] = inc;
    __syncthreads();
    if (w == 0) {
        int s = (lane < 8) ? wsum[lane] : 0;
#pragma unroll
        for (int off = 1; off < 8; off <<= 1) {
            int n = __shfl_up_sync(0xffffffff, s, off);
            if (lane >= off) s += n;
        }
        if (lane < 8) wsum[lane] = s;   // inclusive warp sums
    }
    __syncthreads();
    const int wbase = (w > 0) ? wsum[w - 1] : 0;
    const int exc = wbase + inc - tot;
    if (base + 0 < NN) rp[base + 0] = exc;
    if (base + 1 < NN) rp[base + 1] = exc + v0;
    if (base + 2 < NN) rp[base + 2] = exc + v0 + v1;
    if (base + 3 < NN) rp[base + 3] = exc + v0 + v1 + v2;
    if (t == 255) bs[blockIdx.x] = wbase + inc;   // block total
}

__global__ void scan2_kernel(int* __restrict__ bs) {
    __shared__ int ws[4];
    const int t = threadIdx.x, lane = t & 31, w = t >> 5;
    int v = (t < NB_SCAN) ? bs[t] : 0;
    int inc = v;
#pragma unroll
    for (int off = 1; off < 32; off <<= 1) {
        int n = __shfl_up_sync(0xffffffff, inc, off);
        if (lane >= off) inc += n;
    }
    if (lane == 31) ws[w] = inc;
    __syncthreads();
    if (w == 0 && lane < 4) {
        int s = ws[lane];
#pragma unroll
        for (int off = 1; off < 4; off <<= 1) {
            int n = __shfl_up_sync(0x0000000f, s, off);
            if (lane >= off) s += n;
        }
        ws[lane] = s;
    }
    __syncthreads();
    const int wbase = (w > 0) ? ws[w - 1] : 0;
    if (t < NB_SCAN) bs[t] = wbase + inc - v;   // exclusive
}

__global__ void scan3_kernel(int* __restrict__ rp,
                             int* __restrict__ pos,
                             const int* __restrict__ bs) {
    const int i = blockIdx.x * blockDim.x + threadIdx.x;
    if (i < NN) {
        const int v = rp[i] + bs[i >> 10];
        rp[i] = v;
        pos[i] = v;
    }
    if (i == 0) rp[NN] = NE;
}

__global__ void fill_kernel(const void* __restrict__ edges,
                            int* __restrict__ pos,
                            int* __restrict__ srcs) {
    const int is64 = g_is64;
    const long long* e64 = (const long long*)edges;
    const int*       e32 = (const int*)edges;
    int i = blockIdx.x * blockDim.x + threadIdx.x;
    const int stride = gridDim.x * blockDim.x;
    for (; i < NE; i += stride) {
        int src, dst;
        if (is64) { src = (int)e64[i]; dst = (int)e64[NE + i]; }
        else      { src = e32[i];      dst = e32[NE + i]; }
        const int p = atomicAdd(&pos[dst], 1);
        srcs[p] = src;
    }
}

// ---------------------------------------------------------------------------
// Gather aggregation: warp per dst node. Each lane owns 4 contiguous floats.
// Writes the MEAN directly (inv_deg applied here).
// ---------------------------------------------------------------------------
__global__ void gather_kernel(const float4* __restrict__ xin,
                              const int* __restrict__ rp,
                              const int* __restrict__ srcs,
                              float4* __restrict__ agg) {
    const int warp = (blockIdx.x * blockDim.x + threadIdx.x) >> 5;
    const int lane = threadIdx.x & 31;
    if (warp >= NN) return;
    const int s = rp[warp];
    const int e = rp[warp + 1];
    float4 acc = make_float4(0.f, 0.f, 0.f, 0.f);
    int i = s;
    // unroll-by-2 for load-level parallelism
    for (; i + 1 < e; i += 2) {
        const int s0 = srcs[i];
        const int s1 = srcs[i + 1];
        float4 v0 = __ldg(&xin[(size_t)s0 * (DD / 4) + lane]);
        float4 v1 = __ldg(&xin[(size_t)s1 * (DD / 4) + lane]);
        acc.x += v0.x + v1.x;
        acc.y += v0.y + v1.y;
        acc.z += v0.z + v1.z;
        acc.w += v0.w + v1.w;
    }
    if (i < e) {
        float4 v = __ldg(&xin[(size_t)srcs[i] * (DD / 4) + lane]);
        acc.x += v.x; acc.y += v.y; acc.z += v.z; acc.w += v.w;
    }
    const float inv = 1.0f / fmaxf((float)(e - s), 1.0f);
    acc.x *= inv; acc.y *= inv; acc.z *= inv; acc.w *= inv;
    agg[(size_t)warp * (DD / 4) + lane] = acc;
}

// ---------------------------------------------------------------------------
// Node update:  out = agg_mean @ Wl^T + bias + xr @ Wr^T  [+ relu]
// Fused SGEMM: M=NN, N=128, K=256. BM=128, BN=128, BK=16, 256 thr, 8x8 tile.
// ---------------------------------------------------------------------------
__global__ __launch_bounds__(256, 2)
void node_kernel(const float* __restrict__ agg,
                 const float* __restrict__ xr,
                 const float* __restrict__ Wl,
                 const float* __restrict__ Wr,
                 const float* __restrict__ bias,
                 float* __restrict__ out,
                 int do_relu)
{
    __shared__ float As[16][132];
    __shared__ float Bs[16][132];

    const int t    = threadIdx.x;
    const int trow = t >> 4;
    const int tcol = t & 15;
    const int lrow = t & 127;
    const int koff = (t >> 7) << 3;
    const int row0 = blockIdx.x << 7;
    const int grow = row0 + lrow;
    const bool rv  = grow < NN;

    float acc[8][8];
#pragma unroll
    for (int i = 0; i < 8; ++i)
#pragma unroll
        for (int j = 0; j < 8; ++j) acc[i][j] = 0.f;

#pragma unroll
    for (int half = 0; half < 2; ++half) {
        const float* Asrc = half ? xr : agg;
        const float* Wsrc = half ? Wr : Wl;

#pragma unroll 1
        for (int k0 = 0; k0 < 128; k0 += 16) {
            float4 v0 = make_float4(0.f, 0.f, 0.f, 0.f), v1 = v0;
            if (rv) {
                const float4* p = (const float4*)(Asrc + (size_t)grow * DD + k0 + koff);
                v0 = p[0];
                v1 = p[1];
            }
            As[koff + 0][lrow] = v0.x;
            As[koff + 1][lrow] = v0.y;
            As[koff + 2][lrow] = v0.z;
            As[koff + 3][lrow] = v0.w;
            As[koff + 4][lrow] = v1.x;
            As[koff + 5][lrow] = v1.y;
            As[koff + 6][lrow] = v1.z;
            As[koff + 7][lrow] = v1.w;

            const float4* q = (const float4*)(Wsrc + (size_t)lrow * DD + k0 + koff);
            float4 w0 = q[0];
            float4 w1 = q[1];
            Bs[koff + 0][lrow] = w0.x;
            Bs[koff + 1][lrow] = w0.y;
            Bs[koff + 2][lrow] = w0.z;
            Bs[koff + 3][lrow] = w0.w;
            Bs[koff + 4][lrow] = w1.x;
            Bs[koff + 5][lrow] = w1.y;
            Bs[koff + 6][lrow] = w1.z;
            Bs[koff + 7][lrow] = w1.w;

            __syncthreads();

#pragma unroll
            for (int kk = 0; kk < 16; ++kk) {
                float a[8], b[8];
                *(float4*)&a[0] = *(const float4*)&As[kk][(trow << 3) + 0];
                *(float4*)&a[4] = *(const float4*)&As[kk][(trow << 3) + 4];
                *(float4*)&b[0] = *(const float4*)&Bs[kk][(tcol << 3) + 0];
                *(float4*)&b[4] = *(const float4*)&Bs[kk][(tcol << 3) + 4];
#pragma unroll
                for (int i = 0; i < 8; ++i)
#pragma unroll
                    for (int j = 0; j < 8; ++j)
                        acc[i][j] = fmaf(a[i], b[j], acc[i][j]);
            }
            __syncthreads();
        }
    }

    float bv[8];
#pragma unroll
    for (int j = 0; j < 8; ++j) bv[j] = bias[(tcol << 3) + j];

#pragma unroll
    for (int i = 0; i < 8; ++i) {
        const int r = row0 + (trow << 3) + i;
        if (r < NN) {
            float o[8];
#pragma unroll
            for (int j = 0; j < 8; ++j) {
                float v = acc[i][j] + bv[j];
                if (do_relu) v = fmaxf(v, 0.f);
                o[j] = v;
            }
            float* op = out + (size_t)r * DD + (tcol << 3);
            *(float4*)(op + 0) = *(float4*)&o[0];
            *(float4*)(op + 4) = *(float4*)&o[4];
        }
    }
}

// ---------------------------------------------------------------------------
// Launch sequence (default stream, graph-capturable, allocation-free)
// ---------------------------------------------------------------------------
extern "C" void kernel_launch(void* const* d_in, const int* in_sizes, int n_in,
                              void* d_out, int out_size)
{
    const float* x   = (const float*)d_in[0];
    const void*  ei  = d_in[1];
    const float* W1l = (const float*)d_in[2];
    const float* b1  = (const float*)d_in[3];
    const float* W1r = (const float*)d_in[4];
    const float* W2l = (const float*)d_in[5];
    const float* b2  = (const float*)d_in[6];
    const float* W2r = (const float*)d_in[7];
    float* out = (float*)d_out;

    float *agg, *h;
    int *srcs, *rp, *pos, *cnt, *bs;
    cudaGetSymbolAddress((void**)&agg,  g_agg);
    cudaGetSymbolAddress((void**)&h,    g_h);
    cudaGetSymbolAddress((void**)&srcs, g_srcs);
    cudaGetSymbolAddress((void**)&rp,   g_rp);
    cudaGetSymbolAddress((void**)&pos,  g_pos);
    cudaGetSymbolAddress((void**)&cnt,  g_cnt);
    cudaGetSymbolAddress((void**)&bs,   g_bs);

    detect_kernel<<<1, 256>>>((const unsigned int*)ei);

    // ---- CSR build (per call; no caching allowed) ----
    zero_int_kernel<<<64, 256>>>((int4*)cnt, NN / 4);
    hist_kernel<<<2048, 256>>>(ei, cnt);
    scan1_kernel<<<NB_SCAN, 256>>>(cnt, rp, bs);
    scan2_kernel<<<1, 128>>>(bs);
    scan3_kernel<<<(NN + 255) / 256, 256>>>(rp, pos, bs);
    fill_kernel<<<2048, 256>>>(ei, pos, srcs);

    // ---- Layer 1 ----
    gather_kernel<<<(NN * 32 + 255) / 256, 256>>>((const float4*)x, rp, srcs, (float4*)agg);
    node_kernel<<<(NN + 127) / 128, 256>>>(agg, x, W1l, W1r, b1, h, 1);

    // ---- Layer 2 ----
    gather_kernel<<<(NN * 32 + 255) / 256, 256>>>((const float4*)h, rp, srcs, (float4*)agg);
    node_kernel<<<(NN + 127) / 128, 256>>>(agg, h, W2l, W2r, b2, out, 0);
}

// round 9
// speedup vs baseline: 1.9511x; 1.5266x over previous
#include <cuda_runtime.h>
#include <cuda_bf16.h>
#include <cstdint>
#include <cstddef>

#define NN 100000
#define NE 1600000
#define DD 128
#define NPAD 100096          // 782 * 128
#define NTILE 782
#define NB_SCAN 98           // ceil(100000 / 1024)

// ---------------------------------------------------------------------------
// Device scratch (no allocation allowed)
// ---------------------------------------------------------------------------
__device__ __align__(16) __nv_bfloat16 g_xh[(size_t)NPAD * DD];
__device__ __align__(16) __nv_bfloat16 g_xl[(size_t)NPAD * DD];
__device__ __align__(16) __nv_bfloat16 g_hh[(size_t)NPAD * DD];
__device__ __align__(16) __nv_bfloat16 g_hl[(size_t)NPAD * DD];
__device__ __align__(16) __nv_bfloat16 g_aggh[(size_t)NPAD * DD];
__device__ __align__(16) __nv_bfloat16 g_aggl[(size_t)NPAD * DD];
__device__ __align__(16) __nv_bfloat16 g_wpack[8 * 128 * 128];  // plain row-major slots
__device__ int g_srcs[NE];
__device__ int g_rp[NN + 1];
__device__ int g_pos[NN];
__device__ int g_cnt[NN];
__device__ int g_bs[128];
__device__ int g_is64;

// ---------------------------------------------------------------------------
// helpers
// ---------------------------------------------------------------------------
__device__ __forceinline__ uint32_t smem_to_u32(const void* p) {
    uint32_t a;
    asm("{ .reg .u64 t; cvta.to.shared.u64 t, %1; cvt.u32.u64 %0, t; }"
        : "=r"(a) : "l"(p));
    return a;
}
__device__ __forceinline__ unsigned short bfu(__nv_bfloat16 b) { return __bfloat16_as_ushort(b); }
__device__ __forceinline__ float bflo(unsigned u) {
    return __bfloat162float(__ushort_as_bfloat16((unsigned short)(u & 0xFFFF)));
}
__device__ __forceinline__ float bfhi(unsigned u) {
    return __bfloat162float(__ushort_as_bfloat16((unsigned short)(u >> 16)));
}
__device__ __forceinline__ void split2(float a, float b, unsigned& hi, unsigned& lo) {
    __nv_bfloat16 ah = __float2bfloat16(a), bh = __float2bfloat16(b);
    float ar = a - __bfloat162float(ah), br = b - __bfloat162float(bh);
    __nv_bfloat16 al = __float2bfloat16(ar), bl = __float2bfloat16(br);
    hi = (unsigned)bfu(ah) | ((unsigned)bfu(bh) << 16);
    lo = (unsigned)bfu(al) | ((unsigned)bfu(bl) << 16);
}

// ---------------------------------------------------------------------------
// int64/int32 edge dtype detection
// ---------------------------------------------------------------------------
__global__ void detect_kernel(const unsigned int* __restrict__ ebuf) {
    __shared__ int nz;
    if (threadIdx.x == 0) nz = 0;
    __syncthreads();
    for (int i = threadIdx.x; i < 8192; i += blockDim.x)
        if (ebuf[2 * i + 1] != 0u) nz = 1;
    __syncthreads();
    if (threadIdx.x == 0) g_is64 = (nz == 0) ? 1 : 0;
}

__global__ void zero_int_kernel(int4* __restrict__ p, int n4) {
    int i = blockIdx.x * blockDim.x + threadIdx.x;
    const int stride = gridDim.x * blockDim.x;
    const int4 z = make_int4(0, 0, 0, 0);
    for (; i < n4; i += stride) p[i] = z;
}

// ---------------------------------------------------------------------------
// CSR build: histogram -> scan -> fill
// ---------------------------------------------------------------------------
__global__ void hist_kernel(const void* __restrict__ edges, int* __restrict__ cnt) {
    const int is64 = g_is64;
    const long long* e64 = (const long long*)edges;
    const int*       e32 = (const int*)edges;
    int i = blockIdx.x * blockDim.x + threadIdx.x;
    const int stride = gridDim.x * blockDim.x;
    for (; i < NE; i += stride) {
        int dst = is64 ? (int)e64[NE + i] : e32[NE + i];
        atomicAdd(&cnt[dst], 1);
    }
}

__global__ void scan1_kernel(const int* __restrict__ cnt, int* __restrict__ rp,
                             int* __restrict__ bs) {
    __shared__ int wsum[8];
    const int t = threadIdx.x, lane = t & 31, w = t >> 5;
    const int base = blockIdx.x * 1024 + t * 4;
    int v0 = (base + 0 < NN) ? cnt[base + 0] : 0;
    int v1 = (base + 1 < NN) ? cnt[base + 1] : 0;
    int v2 = (base + 2 < NN) ? cnt[base + 2] : 0;
    int v3 = (base + 3 < NN) ? cnt[base + 3] : 0;
    const int tot = v0 + v1 + v2 + v3;
    int inc = tot;
#pragma unroll
    for (int off = 1; off < 32; off <<= 1) {
        int n = __shfl_up_sync(0xffffffff, inc, off);
        if (lane >= off) inc += n;
    }
    if (lane == 31) wsum[w] = inc;
    __syncthreads();
    if (w == 0) {
        int s = (lane < 8) ? wsum[lane] : 0;
#pragma unroll
        for (int off = 1; off < 8; off <<= 1) {
            int n = __shfl_up_sync(0xffffffff, s, off);
            if (lane >= off) s += n;
        }
        if (lane < 8) wsum[lane] = s;
    }
    __syncthreads();
    const int wbase = (w > 0) ? wsum[w - 1] : 0;
    const int exc = wbase + inc - tot;
    if (base + 0 < NN) rp[base + 0] = exc;
    if (base + 1 < NN) rp[base + 1] = exc + v0;
    if (base + 2 < NN) rp[base + 2] = exc + v0 + v1;
    if (base + 3 < NN) rp[base + 3] = exc + v0 + v1 + v2;
    if (t == 255) bs[blockIdx.x] = wbase + inc;
}

__global__ void scan2_kernel(int* __restrict__ bs) {
    __shared__ int ws[4];
    const int t = threadIdx.x, lane = t & 31, w = t >> 5;
    int v = (t < NB_SCAN) ? bs[t] : 0;
    int inc = v;
#pragma unroll
    for (int off = 1; off < 32; off <<= 1) {
        int n = __shfl_up_sync(0xffffffff, inc, off);
        if (lane >= off) inc += n;
    }
    if (lane == 31) ws[w] = inc;
    __syncthreads();
    if (w == 0 && lane < 4) {
        int s = ws[lane];
#pragma unroll
        for (int off = 1; off < 4; off <<= 1) {
            int n = __shfl_up_sync(0x0000000f, s, off);
            if (lane >= off) s += n;
        }
        ws[lane] = s;
    }
    __syncthreads();
    const int wbase = (w > 0) ? ws[w - 1] : 0;
    if (t < NB_SCAN) bs[t] = wbase + inc - v;
}

__global__ void scan3_kernel(int* __restrict__ rp, int* __restrict__ pos,
                             const int* __restrict__ bs) {
    const int i = blockIdx.x * blockDim.x + threadIdx.x;
    if (i < NN) {
        const int v = rp[i] + bs[i >> 10];
        rp[i] = v;
        pos[i] = v;
    }
    if (i == 0) rp[NN] = NE;
}

__global__ void fill_kernel(const void* __restrict__ edges, int* __restrict__ pos,
                            int* __restrict__ srcs) {
    const int is64 = g_is64;
    const long long* e64 = (const long long*)edges;
    const int*       e32 = (const int*)edges;
    int i = blockIdx.x * blockDim.x + threadIdx.x;
    const int stride = gridDim.x * blockDim.x;
    for (; i < NE; i += stride) {
        int src, dst;
        if (is64) { src = (int)e64[i]; dst = (int)e64[NE + i]; }
        else      { src = e32[i];      dst = e32[NE + i]; }
        const int p = atomicAdd(&pos[dst], 1);
        srcs[p] = src;
    }
}

// ---------------------------------------------------------------------------
// x -> (xh, xl) bf16 split
// ---------------------------------------------------------------------------
__global__ void convert_x_kernel(const float4* __restrict__ x,
                                 __nv_bfloat16* __restrict__ xh,
                                 __nv_bfloat16* __restrict__ xl) {
    const int id = blockIdx.x * blockDim.x + threadIdx.x;
    const int row = id >> 5, lane = id & 31;
    if (row >= NN) return;
    float4 v = x[(size_t)row * 32 + lane];
    unsigned h0, l0, h1, l1;
    split2(v.x, v.y, h0, l0);
    split2(v.z, v.w, h1, l1);
    *(uint2*)(xh + (size_t)row * DD + lane * 4) = make_uint2(h0, h1);
    *(uint2*)(xl + (size_t)row * DD + lane * 4) = make_uint2(l0, l1);
}

// ---------------------------------------------------------------------------
// Weight prep: W fp32 [j][k] -> bf16 hi/lo, plain row-major slots.
// Slots: L1: 0=Wl_h, 1=Wr_h, 2=Wl_l, 3=Wr_l; L2: 4-7 same order.
// ---------------------------------------------------------------------------
__global__ void prep_w_kernel(const float* __restrict__ Wl1, const float* __restrict__ Wr1,
                              const float* __restrict__ Wl2, const float* __restrict__ Wr2,
                              __nv_bfloat16* __restrict__ wpack) {
    const int id = blockIdx.x * blockDim.x + threadIdx.x;  // 0..8191
    if (id >= 8192) return;
    const int tIdx = id >> 11;        // which W
    const int rem = id & 2047;
    const int j = rem >> 4, cu = rem & 15;   // row j, 8-elem group cu
    const float* W = (tIdx == 0) ? Wl1 : (tIdx == 1) ? Wr1 : (tIdx == 2) ? Wl2 : Wr2;
    const float4* p = (const float4*)(W + (size_t)j * DD + cu * 8);
    float4 v0 = p[0], v1 = p[1];
    unsigned hs[4], ls[4];
    split2(v0.x, v0.y, hs[0], ls[0]);
    split2(v0.z, v0.w, hs[1], ls[1]);
    split2(v1.x, v1.y, hs[2], ls[2]);
    split2(v1.z, v1.w, hs[3], ls[3]);
    const int hslot = (tIdx >> 1) * 4 + (tIdx & 1);
    const int lslot = hslot + 2;
    const size_t off = (size_t)j * DD + cu * 8;
    *(uint4*)(wpack + (size_t)hslot * 16384 + off) = make_uint4(hs[0], hs[1], hs[2], hs[3]);
    *(uint4*)(wpack + (size_t)lslot * 16384 + off) = make_uint4(ls[0], ls[1], ls[2], ls[3]);
}

// ---------------------------------------------------------------------------
// Gather (fp32 source): warp per dst node -> mean -> bf16 hi/lo
// ---------------------------------------------------------------------------
__global__ void gather_f32_kernel(const float4* __restrict__ xin,
                                  const int* __restrict__ rp,
                                  const int* __restrict__ srcs,
                                  __nv_bfloat16* __restrict__ aggh,
                                  __nv_bfloat16* __restrict__ aggl) {
    const int warp = (blockIdx.x * blockDim.x + threadIdx.x) >> 5;
    const int lane = threadIdx.x & 31;
    if (warp >= NN) return;
    const int s = rp[warp], e = rp[warp + 1];
    float4 acc = make_float4(0.f, 0.f, 0.f, 0.f);
    int i = s;
    for (; i + 1 < e; i += 2) {
        const int s0 = srcs[i], s1 = srcs[i + 1];
        float4 v0 = __ldg(&xin[(size_t)s0 * 32 + lane]);
        float4 v1 = __ldg(&xin[(size_t)s1 * 32 + lane]);
        acc.x += v0.x + v1.x; acc.y += v0.y + v1.y;
        acc.z += v0.z + v1.z; acc.w += v0.w + v1.w;
    }
    if (i < e) {
        float4 v = __ldg(&xin[(size_t)srcs[i] * 32 + lane]);
        acc.x += v.x; acc.y += v.y; acc.z += v.z; acc.w += v.w;
    }
    const float inv = 1.0f / fmaxf((float)(e - s), 1.0f);
    acc.x *= inv; acc.y *= inv; acc.z *= inv; acc.w *= inv;
    unsigned h0, l0, h1, l1;
    split2(acc.x, acc.y, h0, l0);
    split2(acc.z, acc.w, h1, l1);
    *(uint2*)(aggh + (size_t)warp * DD + lane * 4) = make_uint2(h0, h1);
    *(uint2*)(aggl + (size_t)warp * DD + lane * 4) = make_uint2(l0, l1);
}

// ---------------------------------------------------------------------------
// Gather (bf16 hi/lo source): warp per dst node -> mean -> bf16 hi/lo
// ---------------------------------------------------------------------------
__global__ void gather_bf_kernel(const __nv_bfloat16* __restrict__ hh,
                                 const __nv_bfloat16* __restrict__ hl,
                                 const int* __restrict__ rp,
                                 const int* __restrict__ srcs,
                                 __nv_bfloat16* __restrict__ aggh,
                                 __nv_bfloat16* __restrict__ aggl) {
    const int warp = (blockIdx.x * blockDim.x + threadIdx.x) >> 5;
    const int lane = threadIdx.x & 31;
    if (warp >= NN) return;
    const int s = rp[warp], e = rp[warp + 1];
    float4 acc = make_float4(0.f, 0.f, 0.f, 0.f);
    for (int i = s; i < e; ++i) {
        const size_t off = (size_t)srcs[i] * DD + lane * 4;
        uint2 uh = __ldg((const uint2*)(hh + off));
        uint2 ul = __ldg((const uint2*)(hl + off));
        acc.x += bflo(uh.x) + bflo(ul.x);
        acc.y += bfhi(uh.x) + bfhi(ul.x);
        acc.z += bflo(uh.y) + bflo(ul.y);
        acc.w += bfhi(uh.y) + bfhi(ul.y);
    }
    const float inv = 1.0f / fmaxf((float)(e - s), 1.0f);
    acc.x *= inv; acc.y *= inv; acc.z *= inv; acc.w *= inv;
    unsigned h0, l0, h1, l1;
    split2(acc.x, acc.y, h0, l0);
    split2(acc.z, acc.w, h1, l1);
    *(uint2*)(aggh + (size_t)warp * DD + lane * 4) = make_uint2(h0, h1);
    *(uint2*)(aggl + (size_t)warp * DD + lane * 4) = make_uint2(l0, l1);
}

// ---------------------------------------------------------------------------
// mma.sync (HMMA) node GEMM:  out = [agg|x] @ [Wl;Wr]^T + bias, split-bf16,
// 3 terms (Ah.Bh + Al.Bh + Ah.Bl) => 12 chunks of K=64.
// CTA: 128x128 C-tile; 8 warps in 2x4, each 64x32 warp tile.
// SMEM rows padded to 144B (36 words) => conflict-free ldmatrix.
// ---------------------------------------------------------------------------
#define PADB 144

__global__ void __launch_bounds__(256, 2)
node_mma_kernel(const __nv_bfloat16* __restrict__ a0,   // agg_h
                const __nv_bfloat16* __restrict__ a1,   // x_h / h_h
                const __nv_bfloat16* __restrict__ a2,   // agg_l
                const __nv_bfloat16* __restrict__ a3,   // x_l / h_l
                const __nv_bfloat16* __restrict__ wpack,  // layer's 4 slots
                const float* __restrict__ bias,
                float* __restrict__ outf,
                __nv_bfloat16* __restrict__ oh,
                __nv_bfloat16* __restrict__ ol,
                int relu_split)
{
    __shared__ char sA[128 * PADB];
    __shared__ char sB[128 * PADB];

    const int tid  = threadIdx.x;
    const int wid  = tid >> 5;
    const int lane = tid & 31;
    const int wm   = wid >> 2;          // 0..1
    const int wn   = wid & 3;           // 0..3
    const int row0 = blockIdx.x << 7;

    const uint32_t uA = smem_to_u32(sA);
    const uint32_t uB = smem_to_u32(sB);

    float acc[4][4][4];
#pragma unroll
    for (int mt = 0; mt < 4; ++mt)
#pragma unroll
        for (int nt = 0; nt < 4; ++nt)
#pragma unroll
            for (int q = 0; q < 4; ++q) acc[mt][nt][q] = 0.f;

    // per-lane ldmatrix address offsets (bytes), constant over chunks
    const int a_row = wm * 64 + (lane & 15);           // + mt*16
    const int a_kb  = ((lane >> 4) & 1) << 4;          // 0 or 16 bytes
    const int b_row = wn * 32 + (lane & 7);            // + nt*8
    const int b_kb  = ((lane >> 3) & 1) << 4;          // 0 or 16 (lanes 0-15 used)

#pragma unroll 1
    for (int c = 0; c < 12; ++c) {
        const int term = c >> 2;           // 0: Ah.Bh, 1: Al.Bh, 2: Ah.Bl
        const int idx  = c & 3;
        const int half = idx >> 1;          // 0: agg/Wl part, 1: x/Wr part
        const int ko   = (idx & 1) << 6;    // 0 or 64
        const __nv_bfloat16* A = (term == 1) ? (half ? a3 : a2)
                                             : (half ? a1 : a0);
        const int bslot = ((term == 2) ? 2 : 0) + half;
        const __nv_bfloat16* As = A + (size_t)row0 * DD + ko;
        const __nv_bfloat16* Bs = wpack + (size_t)bslot * 16384 + ko;

        // ---- load A chunk: 128 rows x 64 bf16 -> padded smem ----
#pragma unroll
        for (int i = 0; i < 4; ++i) {
            const int u = i * 256 + tid;    // 0..1023
            const int r = u >> 3, cc = u & 7;
            uint4 v = *(const uint4*)(As + (size_t)r * DD + cc * 8);
            *(uint4*)(sA + r * PADB + cc * 16) = v;
        }
        // ---- load B chunk: 128 n-rows x 64 bf16 -> padded smem ----
#pragma unroll
        for (int i = 0; i < 4; ++i) {
            const int u = i * 256 + tid;
            const int r = u >> 3, cc = u & 7;
            uint4 v = *(const uint4*)(Bs + (size_t)r * DD + cc * 8);
            *(uint4*)(sB + r * PADB + cc * 16) = v;
        }
        __syncthreads();

        // ---- 4 k16 steps ----
#pragma unroll
        for (int ks = 0; ks < 4; ++ks) {
            uint32_t af[4][4];
#pragma unroll
            for (int mt = 0; mt < 4; ++mt) {
                const uint32_t addr = uA + (a_row + mt * 16) * PADB + ks * 32 + a_kb;
                asm volatile("ldmatrix.sync.aligned.m8n8.x4.shared.b16 {%0,%1,%2,%3}, [%4];"
                             : "=r"(af[mt][0]), "=r"(af[mt][1]),
                               "=r"(af[mt][2]), "=r"(af[mt][3])
                             : "r"(addr));
            }
            uint32_t bf[4][2];
#pragma unroll
            for (int nt = 0; nt < 4; ++nt) {
                const uint32_t addr = uB + (b_row + nt * 8) * PADB + ks * 32 + b_kb;
                asm volatile("ldmatrix.sync.aligned.m8n8.x2.shared.b16 {%0,%1}, [%2];"
                             : "=r"(bf[nt][0]), "=r"(bf[nt][1])
                             : "r"(addr));
            }
#pragma unroll
            for (int mt = 0; mt < 4; ++mt)
#pragma unroll
                for (int nt = 0; nt < 4; ++nt) {
                    asm volatile(
                        "mma.sync.aligned.m16n8k16.row.col.f32.bf16.bf16.f32 "
                        "{%0,%1,%2,%3}, {%4,%5,%6,%7}, {%8,%9}, {%0,%1,%2,%3};"
                        : "+f"(acc[mt][nt][0]), "+f"(acc[mt][nt][1]),
                          "+f"(acc[mt][nt][2]), "+f"(acc[mt][nt][3])
                        : "r"(af[mt][0]), "r"(af[mt][1]),
                          "r"(af[mt][2]), "r"(af[mt][3]),
                          "r"(bf[nt][0]), "r"(bf[nt][1]));
                }
        }
        __syncthreads();
    }

    // ---- epilogue ----
    const int col_base = wn * 32 + ((lane & 3) << 1);
    float bv[4][2];
#pragma unroll
    for (int nt = 0; nt < 4; ++nt) {
        bv[nt][0] = __ldg(bias + col_base + nt * 8);
        bv[nt][1] = __ldg(bias + col_base + nt * 8 + 1);
    }

#pragma unroll
    for (int mt = 0; mt < 4; ++mt) {
        const int r0 = row0 + wm * 64 + mt * 16 + (lane >> 2);
        const int r1 = r0 + 8;
#pragma unroll
        for (int nt = 0; nt < 4; ++nt) {
            const int col = col_base + nt * 8;
            float v0 = acc[mt][nt][0] + bv[nt][0];
            float v1 = acc[mt][nt][1] + bv[nt][1];
            float v2 = acc[mt][nt][2] + bv[nt][0];
            float v3 = acc[mt][nt][3] + bv[nt][1];
            if (relu_split) {
                v0 = fmaxf(v0, 0.f); v1 = fmaxf(v1, 0.f);
                v2 = fmaxf(v2, 0.f); v3 = fmaxf(v3, 0.f);
                unsigned h01, l01, h23, l23;
                split2(v0, v1, h01, l01);
                split2(v2, v3, h23, l23);
                if (r0 < NN) {
                    *(unsigned*)(oh + (size_t)r0 * DD + col) = h01;
                    *(unsigned*)(ol + (size_t)r0 * DD + col) = l01;
                }
                if (r1 < NN) {
                    *(unsigned*)(oh + (size_t)r1 * DD + col) = h23;
                    *(unsigned*)(ol + (size_t)r1 * DD + col) = l23;
                }
            } else {
                if (r0 < NN) *(float2*)(outf + (size_t)r0 * DD + col) = make_float2(v0, v1);
                if (r1 < NN) *(float2*)(outf + (size_t)r1 * DD + col) = make_float2(v2, v3);
            }
        }
    }
}

// ---------------------------------------------------------------------------
// Launch sequence (default stream, graph-capturable, allocation-free)
// ---------------------------------------------------------------------------
extern "C" void kernel_launch(void* const* d_in, const int* in_sizes, int n_in,
                              void* d_out, int out_size)
{
    const float* x   = (const float*)d_in[0];
    const void*  ei  = d_in[1];
    const float* W1l = (const float*)d_in[2];
    const float* b1  = (const float*)d_in[3];
    const float* W1r = (const float*)d_in[4];
    const float* W2l = (const float*)d_in[5];
    const float* b2  = (const float*)d_in[6];
    const float* W2r = (const float*)d_in[7];
    float* out = (float*)d_out;

    __nv_bfloat16 *xh, *xl, *hh, *hl, *aggh, *aggl, *wpack;
    int *srcs, *rp, *pos, *cnt, *bs;
    cudaGetSymbolAddress((void**)&xh,    g_xh);
    cudaGetSymbolAddress((void**)&xl,    g_xl);
    cudaGetSymbolAddress((void**)&hh,    g_hh);
    cudaGetSymbolAddress((void**)&hl,    g_hl);
    cudaGetSymbolAddress((void**)&aggh,  g_aggh);
    cudaGetSymbolAddress((void**)&aggl,  g_aggl);
    cudaGetSymbolAddress((void**)&wpack, g_wpack);
    cudaGetSymbolAddress((void**)&srcs,  g_srcs);
    cudaGetSymbolAddress((void**)&rp,    g_rp);
    cudaGetSymbolAddress((void**)&pos,   g_pos);
    cudaGetSymbolAddress((void**)&cnt,   g_cnt);
    cudaGetSymbolAddress((void**)&bs,    g_bs);

    detect_kernel<<<1, 256>>>((const unsigned int*)ei);

    // CSR build
    zero_int_kernel<<<64, 256>>>((int4*)cnt, NN / 4);
    hist_kernel<<<2048, 256>>>(ei, cnt);
    scan1_kernel<<<NB_SCAN, 256>>>(cnt, rp, bs);
    scan2_kernel<<<1, 128>>>(bs);
    scan3_kernel<<<(NN + 255) / 256, 256>>>(rp, pos, bs);
    fill_kernel<<<2048, 256>>>(ei, pos, srcs);

    // bf16 conversions / weight packing
    convert_x_kernel<<<(NN * 32 + 255) / 256, 256>>>((const float4*)x, xh, xl);
    prep_w_kernel<<<32, 256>>>(W1l, W1r, W2l, W2r, wpack);

    // Layer 1
    gather_f32_kernel<<<(NN * 32 + 255) / 256, 256>>>((const float4*)x, rp, srcs, aggh, aggl);
    node_mma_kernel<<<NTILE, 256>>>(aggh, xh, aggl, xl,
                                    wpack, b1, nullptr, hh, hl, 1);

    // Layer 2
    gather_bf_kernel<<<(NN * 32 + 255) / 256, 256>>>(hh, hl, rp, srcs, aggh, aggl);
    node_mma_kernel<<<NTILE, 256>>>(aggh, hh, aggl, hl,
                                    wpack + 4 * 16384, b2, out, nullptr, nullptr, 0);
}

// round 10
// speedup vs baseline: 2.2292x; 1.1425x over previous
#include <cuda_runtime.h>
#include <cuda_bf16.h>
#include <cstdint>
#include <cstddef>

#define NN 100000
#define NE 1600000
#define DD 128
#define NPAD 100096          // 782 * 128
#define NTILE 782
#define NB_SCAN 98           // ceil(100000 / 1024)

// ---------------------------------------------------------------------------
// Device scratch (no allocation allowed)
// ---------------------------------------------------------------------------
__device__ __align__(16) __nv_bfloat16 g_xh[(size_t)NPAD * DD];
__device__ __align__(16) __nv_bfloat16 g_xl[(size_t)NPAD * DD];
__device__ __align__(16) __nv_bfloat16 g_hh[(size_t)NPAD * DD];
__device__ __align__(16) __nv_bfloat16 g_hl[(size_t)NPAD * DD];
__device__ __align__(16) __nv_bfloat16 g_aggh[(size_t)NPAD * DD];
__device__ __align__(16) __nv_bfloat16 g_aggl[(size_t)NPAD * DD];
__device__ __align__(16) __nv_bfloat16 g_wpack[8 * 128 * 128];  // plain row-major slots
__device__ int g_srcs[NE];
__device__ int g_rp[NN + 1];
__device__ int g_pos[NN];
__device__ int g_cnt[NN];
__device__ int g_bs[128];
__device__ int g_is64;

// ---------------------------------------------------------------------------
// helpers
// ---------------------------------------------------------------------------
__device__ __forceinline__ uint32_t smem_to_u32(const void* p) {
    uint32_t a;
    asm("{ .reg .u64 t; cvta.to.shared.u64 t, %1; cvt.u32.u64 %0, t; }"
        : "=r"(a) : "l"(p));
    return a;
}
__device__ __forceinline__ unsigned short bfu(__nv_bfloat16 b) { return __bfloat16_as_ushort(b); }
__device__ __forceinline__ float bflo(unsigned u) {
    return __bfloat162float(__ushort_as_bfloat16((unsigned short)(u & 0xFFFF)));
}
__device__ __forceinline__ float bfhi(unsigned u) {
    return __bfloat162float(__ushort_as_bfloat16((unsigned short)(u >> 16)));
}
__device__ __forceinline__ void split2(float a, float b, unsigned& hi, unsigned& lo) {
    __nv_bfloat16 ah = __float2bfloat16(a), bh = __float2bfloat16(b);
    float ar = a - __bfloat162float(ah), br = b - __bfloat162float(bh);
    __nv_bfloat16 al = __float2bfloat16(ar), bl = __float2bfloat16(br);
    hi = (unsigned)bfu(ah) | ((unsigned)bfu(bh) << 16);
    lo = (unsigned)bfu(al) | ((unsigned)bfu(bl) << 16);
}
__device__ __forceinline__ void cp_async16(uint32_t saddr, const void* gptr) {
    asm volatile("cp.async.cg.shared.global [%0], [%1], 16;"
                 :: "r"(saddr), "l"(gptr));
}
#define CP_COMMIT() asm volatile("cp.async.commit_group;" ::: "memory")
#define CP_WAIT1()  asm volatile("cp.async.wait_group 1;" ::: "memory")
#define CP_WAIT0()  asm volatile("cp.async.wait_group 0;" ::: "memory")

// ---------------------------------------------------------------------------
// int64/int32 edge dtype detection
// ---------------------------------------------------------------------------
__global__ void detect_kernel(const unsigned int* __restrict__ ebuf) {
    __shared__ int nz;
    if (threadIdx.x == 0) nz = 0;
    __syncthreads();
    for (int i = threadIdx.x; i < 8192; i += blockDim.x)
        if (ebuf[2 * i + 1] != 0u) nz = 1;
    __syncthreads();
    if (threadIdx.x == 0) g_is64 = (nz == 0) ? 1 : 0;
}

__global__ void zero_int_kernel(int4* __restrict__ p, int n4) {
    int i = blockIdx.x * blockDim.x + threadIdx.x;
    const int stride = gridDim.x * blockDim.x;
    const int4 z = make_int4(0, 0, 0, 0);
    for (; i < n4; i += stride) p[i] = z;
}

// ---------------------------------------------------------------------------
// CSR build: histogram -> scan -> fill
// ---------------------------------------------------------------------------
__global__ void hist_kernel(const void* __restrict__ edges, int* __restrict__ cnt) {
    const int is64 = g_is64;
    const long long* e64 = (const long long*)edges;
    const int*       e32 = (const int*)edges;
    int i = blockIdx.x * blockDim.x + threadIdx.x;
    const int stride = gridDim.x * blockDim.x;
    for (; i < NE; i += stride) {
        int dst = is64 ? (int)e64[NE + i] : e32[NE + i];
        atomicAdd(&cnt[dst], 1);
    }
}

__global__ void scan1_kernel(const int* __restrict__ cnt, int* __restrict__ rp,
                             int* __restrict__ bs) {
    __shared__ int wsum[8];
    const int t = threadIdx.x, lane = t & 31, w = t >> 5;
    const int base = blockIdx.x * 1024 + t * 4;
    int v0 = (base + 0 < NN) ? cnt[base + 0] : 0;
    int v1 = (base + 1 < NN) ? cnt[base + 1] : 0;
    int v2 = (base + 2 < NN) ? cnt[base + 2] : 0;
    int v3 = (base + 3 < NN) ? cnt[base + 3] : 0;
    const int tot = v0 + v1 + v2 + v3;
    int inc = tot;
#pragma unroll
    for (int off = 1; off < 32; off <<= 1) {
        int n = __shfl_up_sync(0xffffffff, inc, off);
        if (lane >= off) inc += n;
    }
    if (lane == 31) wsum[w] = inc;
    __syncthreads();
    if (w == 0) {
        int s = (lane < 8) ? wsum[lane] : 0;
#pragma unroll
        for (int off = 1; off < 8; off <<= 1) {
            int n = __shfl_up_sync(0xffffffff, s, off);
            if (lane >= off) s += n;
        }
        if (lane < 8) wsum[lane] = s;
    }
    __syncthreads();
    const int wbase = (w > 0) ? wsum[w - 1] : 0;
    const int exc = wbase + inc - tot;
    if (base + 0 < NN) rp[base + 0] = exc;
    if (base + 1 < NN) rp[base + 1] = exc + v0;
    if (base + 2 < NN) rp[base + 2] = exc + v0 + v1;
    if (base + 3 < NN) rp[base + 3] = exc + v0 + v1 + v2;
    if (t == 255) bs[blockIdx.x] = wbase + inc;
}

__global__ void scan2_kernel(int* __restrict__ bs) {
    __shared__ int ws[4];
    const int t = threadIdx.x, lane = t & 31, w = t >> 5;
    int v = (t < NB_SCAN) ? bs[t] : 0;
    int inc = v;
#pragma unroll
    for (int off = 1; off < 32; off <<= 1) {
        int n = __shfl_up_sync(0xffffffff, inc, off);
        if (lane >= off) inc += n;
    }
    if (lane == 31) ws[w] = inc;
    __syncthreads();
    if (w == 0 && lane < 4) {
        int s = ws[lane];
#pragma unroll
        for (int off = 1; off < 4; off <<= 1) {
            int n = __shfl_up_sync(0x0000000f, s, off);
            if (lane >= off) s += n;
        }
        ws[lane] = s;
    }
    __syncthreads();
    const int wbase = (w > 0) ? ws[w - 1] : 0;
    if (t < NB_SCAN) bs[t] = wbase + inc - v;
}

__global__ void scan3_kernel(int* __restrict__ rp, int* __restrict__ pos,
                             const int* __restrict__ bs) {
    const int i = blockIdx.x * blockDim.x + threadIdx.x;
    if (i < NN) {
        const int v = rp[i] + bs[i >> 10];
        rp[i] = v;
        pos[i] = v;
    }
    if (i == 0) rp[NN] = NE;
}

__global__ void fill_kernel(const void* __restrict__ edges, int* __restrict__ pos,
                            int* __restrict__ srcs) {
    const int is64 = g_is64;
    const long long* e64 = (const long long*)edges;
    const int*       e32 = (const int*)edges;
    int i = blockIdx.x * blockDim.x + threadIdx.x;
    const int stride = gridDim.x * blockDim.x;
    for (; i < NE; i += stride) {
        int src, dst;
        if (is64) { src = (int)e64[i]; dst = (int)e64[NE + i]; }
        else      { src = e32[i];      dst = e32[NE + i]; }
        const int p = atomicAdd(&pos[dst], 1);
        srcs[p] = src;
    }
}

// ---------------------------------------------------------------------------
// x -> (xh, xl) bf16 split
// ---------------------------------------------------------------------------
__global__ void convert_x_kernel(const float4* __restrict__ x,
                                 __nv_bfloat16* __restrict__ xh,
                                 __nv_bfloat16* __restrict__ xl) {
    const int id = blockIdx.x * blockDim.x + threadIdx.x;
    const int row = id >> 5, lane = id & 31;
    if (row >= NN) return;
    float4 v = x[(size_t)row * 32 + lane];
    unsigned h0, l0, h1, l1;
    split2(v.x, v.y, h0, l0);
    split2(v.z, v.w, h1, l1);
    *(uint2*)(xh + (size_t)row * DD + lane * 4) = make_uint2(h0, h1);
    *(uint2*)(xl + (size_t)row * DD + lane * 4) = make_uint2(l0, l1);
}

// ---------------------------------------------------------------------------
// Weight prep: W fp32 [j][k] -> bf16 hi/lo, plain row-major slots.
// Slots: L1: 0=Wl_h, 1=Wr_h, 2=Wl_l, 3=Wr_l; L2: 4-7 same order.
// ---------------------------------------------------------------------------
__global__ void prep_w_kernel(const float* __restrict__ Wl1, const float* __restrict__ Wr1,
                              const float* __restrict__ Wl2, const float* __restrict__ Wr2,
                              __nv_bfloat16* __restrict__ wpack) {
    const int id = blockIdx.x * blockDim.x + threadIdx.x;  // 0..8191
    if (id >= 8192) return;
    const int tIdx = id >> 11;        // which W
    const int rem = id & 2047;
    const int j = rem >> 4, cu = rem & 15;   // row j, 8-elem group cu
    const float* W = (tIdx == 0) ? Wl1 : (tIdx == 1) ? Wr1 : (tIdx == 2) ? Wl2 : Wr2;
    const float4* p = (const float4*)(W + (size_t)j * DD + cu * 8);
    float4 v0 = p[0], v1 = p[1];
    unsigned hs[4], ls[4];
    split2(v0.x, v0.y, hs[0], ls[0]);
    split2(v0.z, v0.w, hs[1], ls[1]);
    split2(v1.x, v1.y, hs[2], ls[2]);
    split2(v1.z, v1.w, hs[3], ls[3]);
    const int hslot = (tIdx >> 1) * 4 + (tIdx & 1);
    const int lslot = hslot + 2;
    const size_t off = (size_t)j * DD + cu * 8;
    *(uint4*)(wpack + (size_t)hslot * 16384 + off) = make_uint4(hs[0], hs[1], hs[2], hs[3]);
    *(uint4*)(wpack + (size_t)lslot * 16384 + off) = make_uint4(ls[0], ls[1], ls[2], ls[3]);
}

// ---------------------------------------------------------------------------
// Gather (fp32 source): warp per dst node -> mean -> bf16 hi/lo
// ---------------------------------------------------------------------------
__global__ void gather_f32_kernel(const float4* __restrict__ xin,
                                  const int* __restrict__ rp,
                                  const int* __restrict__ srcs,
                                  __nv_bfloat16* __restrict__ aggh,
                                  __nv_bfloat16* __restrict__ aggl) {
    const int warp = (blockIdx.x * blockDim.x + threadIdx.x) >> 5;
    const int lane = threadIdx.x & 31;
    if (warp >= NN) return;
    const int s = rp[warp], e = rp[warp + 1];
    float4 acc = make_float4(0.f, 0.f, 0.f, 0.f);
    int i = s;
    for (; i + 1 < e; i += 2) {
        const int s0 = srcs[i], s1 = srcs[i + 1];
        float4 v0 = __ldg(&xin[(size_t)s0 * 32 + lane]);
        float4 v1 = __ldg(&xin[(size_t)s1 * 32 + lane]);
        acc.x += v0.x + v1.x; acc.y += v0.y + v1.y;
        acc.z += v0.z + v1.z; acc.w += v0.w + v1.w;
    }
    if (i < e) {
        float4 v = __ldg(&xin[(size_t)srcs[i] * 32 + lane]);
        acc.x += v.x; acc.y += v.y; acc.z += v.z; acc.w += v.w;
    }
    const float inv = 1.0f / fmaxf((float)(e - s), 1.0f);
    acc.x *= inv; acc.y *= inv; acc.z *= inv; acc.w *= inv;
    unsigned h0, l0, h1, l1;
    split2(acc.x, acc.y, h0, l0);
    split2(acc.z, acc.w, h1, l1);
    *(uint2*)(aggh + (size_t)warp * DD + lane * 4) = make_uint2(h0, h1);
    *(uint2*)(aggl + (size_t)warp * DD + lane * 4) = make_uint2(l0, l1);
}

// ---------------------------------------------------------------------------
// Gather (bf16 hi/lo source): warp per dst node -> mean -> bf16 hi/lo
// ---------------------------------------------------------------------------
__global__ void gather_bf_kernel(const __nv_bfloat16* __restrict__ hh,
                                 const __nv_bfloat16* __restrict__ hl,
                                 const int* __restrict__ rp,
                                 const int* __restrict__ srcs,
                                 __nv_bfloat16* __restrict__ aggh,
                                 __nv_bfloat16* __restrict__ aggl) {
    const int warp = (blockIdx.x * blockDim.x + threadIdx.x) >> 5;
    const int lane = threadIdx.x & 31;
    if (warp >= NN) return;
    const int s = rp[warp], e = rp[warp + 1];
    float4 acc = make_float4(0.f, 0.f, 0.f, 0.f);
    int i = s;
    for (; i + 1 < e; i += 2) {
        const size_t o0 = (size_t)srcs[i] * DD + lane * 4;
        const size_t o1 = (size_t)srcs[i + 1] * DD + lane * 4;
        uint2 uh0 = __ldg((const uint2*)(hh + o0));
        uint2 ul0 = __ldg((const uint2*)(hl + o0));
        uint2 uh1 = __ldg((const uint2*)(hh + o1));
        uint2 ul1 = __ldg((const uint2*)(hl + o1));
        acc.x += bflo(uh0.x) + bflo(ul0.x) + bflo(uh1.x) + bflo(ul1.x);
        acc.y += bfhi(uh0.x) + bfhi(ul0.x) + bfhi(uh1.x) + bfhi(ul1.x);
        acc.z += bflo(uh0.y) + bflo(ul0.y) + bflo(uh1.y) + bflo(ul1.y);
        acc.w += bfhi(uh0.y) + bfhi(ul0.y) + bfhi(uh1.y) + bfhi(ul1.y);
    }
    if (i < e) {
        const size_t off = (size_t)srcs[i] * DD + lane * 4;
        uint2 uh = __ldg((const uint2*)(hh + off));
        uint2 ul = __ldg((const uint2*)(hl + off));
        acc.x += bflo(uh.x) + bflo(ul.x);
        acc.y += bfhi(uh.x) + bfhi(ul.x);
        acc.z += bflo(uh.y) + bflo(ul.y);
        acc.w += bfhi(uh.y) + bfhi(ul.y);
    }
    const float inv = 1.0f / fmaxf((float)(e - s), 1.0f);
    acc.x *= inv; acc.y *= inv; acc.z *= inv; acc.w *= inv;
    unsigned h0, l0, h1, l1;
    split2(acc.x, acc.y, h0, l0);
    split2(acc.z, acc.w, h1, l1);
    *(uint2*)(aggh + (size_t)warp * DD + lane * 4) = make_uint2(h0, h1);
    *(uint2*)(aggl + (size_t)warp * DD + lane * 4) = make_uint2(l0, l1);
}

// ---------------------------------------------------------------------------
// mma.sync (HMMA) node GEMM, cp.async double-buffered, A-reuse schedule.
// out = [agg|x] @ [Wl;Wr]^T + bias, split-bf16 3-term => 12 MMA chunks K=64.
// Chunk order pairs (Ah.Bh, Ah.Bl) so each Ah chunk loads once (8 A loads).
// SMEM: A[2] + B[2] buffers of 128 rows x 144B (padded, conflict-free).
// ---------------------------------------------------------------------------
#define PADB 144
#define ACH  (128 * PADB)          // 18432 bytes per buffer
#define NODE_SMEM (4 * ACH)        // 73728

__global__ void __launch_bounds__(256, 2)
node_mma_kernel(const __nv_bfloat16* __restrict__ a0,   // agg_h
                const __nv_bfloat16* __restrict__ a1,   // x_h / h_h
                const __nv_bfloat16* __restrict__ a2,   // agg_l
                const __nv_bfloat16* __restrict__ a3,   // x_l / h_l
                const __nv_bfloat16* __restrict__ wpack,  // layer's 4 slots
                const float* __restrict__ bias,
                float* __restrict__ outf,
                __nv_bfloat16* __restrict__ oh,
                __nv_bfloat16* __restrict__ ol,
                int relu_split)
{
    extern __shared__ char smem[];
    const uint32_t uS = smem_to_u32(smem);

    const int tid  = threadIdx.x;
    const int wid  = tid >> 5;
    const int lane = tid & 31;
    const int wm   = wid >> 2;          // 0..1
    const int wn   = wid & 3;           // 0..3
    const int row0 = blockIdx.x << 7;

    // chunk schedule (A-reuse pairs first, then Al*Bh term)
    // aSrc: 0=aggh 1=xh 2=aggl 3=xl ; bSlot within layer's wpack
    const int aSrcT[12] = {0,0,0,0, 1,1,1,1, 2,2,3,3};
    const int aKoT [12] = {0,0,64,64, 0,0,64,64, 0,64,0,64};
    const int aNewT[12] = {1,0,1,0, 1,0,1,0, 1,1,1,1};
    const int aBufT[12] = {0,0,1,1, 0,0,1,1, 0,1,0,1};
    const int bSlotT[12]= {0,2,0,2, 1,3,1,3, 0,0,1,1};
    const int bKoT [12] = {0,0,64,64, 0,0,64,64, 0,64,0,64};
    const int bBufT[12] = {0,1,0,1, 0,1,0,1, 0,1,0,1};

    const __nv_bfloat16* aBase[4] = {a0, a1, a2, a3};

    // per-thread load geometry (4 x 16B per 16KB chunk)
    const int lr = tid >> 1;                 // 0..127 row (2 threads/row)
    const int lc = (tid & 1) << 2;           // 0 or 4 (8-elem groups)

    // per-lane ldmatrix geometry
    const int a_row = wm * 64 + (lane & 15);
    const int a_kb  = ((lane >> 4) & 1) << 4;
    const int b_row = wn * 32 + (lane & 7);
    const int b_kb  = ((lane >> 3) & 1) << 4;

    float acc[4][4][4];
#pragma unroll
    for (int mt = 0; mt < 4; ++mt)
#pragma unroll
        for (int nt = 0; nt < 4; ++nt)
#pragma unroll
            for (int q = 0; q < 4; ++q) acc[mt][nt][q] = 0.f;

    // ---- issue chunk-0 loads ----
#pragma unroll
    {
        const __nv_bfloat16* As = aBase[aSrcT[0]] + (size_t)row0 * DD + aKoT[0];
        const __nv_bfloat16* Bs = wpack + (size_t)bSlotT[0] * 16384 + bKoT[0];
#pragma unroll
        for (int i = 0; i < 4; ++i) {
            const int r = (i * 128 + lr) & 127;      // rows 0..127, 2 passes
            const int cc = lc + (i >> 1) * 0;        // placeholder (see below)
            (void)cc; (void)r;
        }
        // 4 x 16B per thread: linear u = i*256+tid -> row u>>3, group u&7
#pragma unroll
        for (int i = 0; i < 4; ++i) {
            const int u = i * 256 + tid;
            const int r = u >> 3, g = u & 7;
            cp_async16(uS + 0 * ACH + r * PADB + g * 16, As + (size_t)r * DD + g * 8);
        }
#pragma unroll
        for (int i = 0; i < 4; ++i) {
            const int u = i * 256 + tid;
            const int r = u >> 3, g = u & 7;
            cp_async16(uS + 2 * ACH + r * PADB + g * 16, Bs + (size_t)r * DD + g * 8);
        }
        CP_COMMIT();
    }

#pragma unroll
    for (int c = 0; c < 12; ++c) {
        // guard buffers that chunk c+1's loads will overwrite (read by c-1)
        __syncthreads();

        if (c < 11) {
            const int n = c + 1;
            if (aNewT[n]) {
                const __nv_bfloat16* As = aBase[aSrcT[n]] + (size_t)row0 * DD + aKoT[n];
                const uint32_t dst = uS + aBufT[n] * ACH;
#pragma unroll
                for (int i = 0; i < 4; ++i) {
                    const int u = i * 256 + tid;
                    const int r = u >> 3, g = u & 7;
                    cp_async16(dst + r * PADB + g * 16, As + (size_t)r * DD + g * 8);
                }
            }
            {
                const __nv_bfloat16* Bs = wpack + (size_t)bSlotT[n] * 16384 + bKoT[n];
                const uint32_t dst = uS + 2 * ACH + bBufT[n] * ACH;
#pragma unroll
                for (int i = 0; i < 4; ++i) {
                    const int u = i * 256 + tid;
                    const int r = u >> 3, g = u & 7;
                    cp_async16(dst + r * PADB + g * 16, Bs + (size_t)r * DD + g * 8);
                }
            }
            CP_COMMIT();
            CP_WAIT1();     // chunk c's group complete
        } else {
            CP_WAIT0();
        }
        __syncthreads();

        const uint32_t uA = uS + aBufT[c] * ACH;
        const uint32_t uB = uS + 2 * ACH + bBufT[c] * ACH;

#pragma unroll
        for (int ks = 0; ks < 4; ++ks) {
            uint32_t af[4][4];
#pragma unroll
            for (int mt = 0; mt < 4; ++mt) {
                const uint32_t addr = uA + (a_row + mt * 16) * PADB + ks * 32 + a_kb;
                asm volatile("ldmatrix.sync.aligned.m8n8.x4.shared.b16 {%0,%1,%2,%3}, [%4];"
                             : "=r"(af[mt][0]), "=r"(af[mt][1]),
                               "=r"(af[mt][2]), "=r"(af[mt][3])
                             : "r"(addr));
            }
            uint32_t bfr[4][2];
#pragma unroll
            for (int nt = 0; nt < 4; ++nt) {
                const uint32_t addr = uB + (b_row + nt * 8) * PADB + ks * 32 + b_kb;
                asm volatile("ldmatrix.sync.aligned.m8n8.x2.shared.b16 {%0,%1}, [%2];"
                             : "=r"(bfr[nt][0]), "=r"(bfr[nt][1])
                             : "r"(addr));
            }
#pragma unroll
            for (int mt = 0; mt < 4; ++mt)
#pragma unroll
                for (int nt = 0; nt < 4; ++nt) {
                    asm volatile(
                        "mma.sync.aligned.m16n8k16.row.col.f32.bf16.bf16.f32 "
                        "{%0,%1,%2,%3}, {%4,%5,%6,%7}, {%8,%9}, {%0,%1,%2,%3};"
                        : "+f"(acc[mt][nt][0]), "+f"(acc[mt][nt][1]),
                          "+f"(acc[mt][nt][2]), "+f"(acc[mt][nt][3])
                        : "r"(af[mt][0]), "r"(af[mt][1]),
                          "r"(af[mt][2]), "r"(af[mt][3]),
                          "r"(bfr[nt][0]), "r"(bfr[nt][1]));
                }
        }
    }

    // ---- epilogue ----
    const int col_base = wn * 32 + ((lane & 3) << 1);
    float bv[4][2];
#pragma unroll
    for (int nt = 0; nt < 4; ++nt) {
        bv[nt][0] = __ldg(bias + col_base + nt * 8);
        bv[nt][1] = __ldg(bias + col_base + nt * 8 + 1);
    }

#pragma unroll
    for (int mt = 0; mt < 4; ++mt) {
        const int r0 = row0 + wm * 64 + mt * 16 + (lane >> 2);
        const int r1 = r0 + 8;
#pragma unroll
        for (int nt = 0; nt < 4; ++nt) {
            const int col = col_base + nt * 8;
            float v0 = acc[mt][nt][0] + bv[nt][0];
            float v1 = acc[mt][nt][1] + bv[nt][1];
            float v2 = acc[mt][nt][2] + bv[nt][0];
            float v3 = acc[mt][nt][3] + bv[nt][1];
            if (relu_split) {
                v0 = fmaxf(v0, 0.f); v1 = fmaxf(v1, 0.f);
                v2 = fmaxf(v2, 0.f); v3 = fmaxf(v3, 0.f);
                unsigned h01, l01, h23, l23;
                split2(v0, v1, h01, l01);
                split2(v2, v3, h23, l23);
                if (r0 < NN) {
                    *(unsigned*)(oh + (size_t)r0 * DD + col) = h01;
                    *(unsigned*)(ol + (size_t)r0 * DD + col) = l01;
                }
                if (r1 < NN) {
                    *(unsigned*)(oh + (size_t)r1 * DD + col) = h23;
                    *(unsigned*)(ol + (size_t)r1 * DD + col) = l23;
                }
            } else {
                if (r0 < NN) *(float2*)(outf + (size_t)r0 * DD + col) = make_float2(v0, v1);
                if (r1 < NN) *(float2*)(outf + (size_t)r1 * DD + col) = make_float2(v2, v3);
            }
        }
    }
}

// ---------------------------------------------------------------------------
// Launch sequence (default stream, graph-capturable, allocation-free)
// ---------------------------------------------------------------------------
extern "C" void kernel_launch(void* const* d_in, const int* in_sizes, int n_in,
                              void* d_out, int out_size)
{
    const float* x   = (const float*)d_in[0];
    const void*  ei  = d_in[1];
    const float* W1l = (const float*)d_in[2];
    const float* b1  = (const float*)d_in[3];
    const float* W1r = (const float*)d_in[4];
    const float* W2l = (const float*)d_in[5];
    const float* b2  = (const float*)d_in[6];
    const float* W2r = (const float*)d_in[7];
    float* out = (float*)d_out;

    __nv_bfloat16 *xh, *xl, *hh, *hl, *aggh, *aggl, *wpack;
    int *srcs, *rp, *pos, *cnt, *bs;
    cudaGetSymbolAddress((void**)&xh,    g_xh);
    cudaGetSymbolAddress((void**)&xl,    g_xl);
    cudaGetSymbolAddress((void**)&hh,    g_hh);
    cudaGetSymbolAddress((void**)&hl,    g_hl);
    cudaGetSymbolAddress((void**)&aggh,  g_aggh);
    cudaGetSymbolAddress((void**)&aggl,  g_aggl);
    cudaGetSymbolAddress((void**)&wpack, g_wpack);
    cudaGetSymbolAddress((void**)&srcs,  g_srcs);
    cudaGetSymbolAddress((void**)&rp,    g_rp);
    cudaGetSymbolAddress((void**)&pos,   g_pos);
    cudaGetSymbolAddress((void**)&cnt,   g_cnt);
    cudaGetSymbolAddress((void**)&bs,    g_bs);

    cudaFuncSetAttribute(node_mma_kernel,
                         cudaFuncAttributeMaxDynamicSharedMemorySize, NODE_SMEM);

    detect_kernel<<<1, 256>>>((const unsigned int*)ei);

    // CSR build
    zero_int_kernel<<<64, 256>>>((int4*)cnt, NN / 4);
    hist_kernel<<<2048, 256>>>(ei, cnt);
    scan1_kernel<<<NB_SCAN, 256>>>(cnt, rp, bs);
    scan2_kernel<<<1, 128>>>(bs);
    scan3_kernel<<<(NN + 255) / 256, 256>>>(rp, pos, bs);
    fill_kernel<<<2048, 256>>>(ei, pos, srcs);

    // bf16 conversions / weight packing
    convert_x_kernel<<<(NN * 32 + 255) / 256, 256>>>((const float4*)x, xh, xl);
    prep_w_kernel<<<32, 256>>>(W1l, W1r, W2l, W2r, wpack);

    // Layer 1
    gather_f32_kernel<<<(NN * 32 + 255) / 256, 256>>>((const float4*)x, rp, srcs, aggh, aggl);
    node_mma_kernel<<<NTILE, 256, NODE_SMEM>>>(aggh, xh, aggl, xl,
                                               wpack, b1, nullptr, hh, hl, 1);

    // Layer 2
    gather_bf_kernel<<<(NN * 32 + 255) / 256, 256>>>(hh, hl, rp, srcs, aggh, aggl);
    node_mma_kernel<<<NTILE, 256, NODE_SMEM>>>(aggh, hh, aggl, hl,
                                               wpack + 4 * 16384, b2, out, nullptr, nullptr, 0);
}

// round 11
// speedup vs baseline: 2.4028x; 1.0779x over previous
#include <cuda_runtime.h>
#include <cuda_bf16.h>
#include <cuda_fp16.h>
#include <cstdint>
#include <cstddef>

#define NN 100000
#define NE 1600000
#define DD 128
#define NPAD 100096          // 782 * 128
#define NTILE 782
#define NB_SCAN 98           // ceil(100000 / 1024)

// ---------------------------------------------------------------------------
// Device scratch (no allocation allowed)
// ---------------------------------------------------------------------------
__device__ __align__(16) __nv_bfloat16 g_xh[(size_t)NPAD * DD];
__device__ __align__(16) __nv_bfloat16 g_xl[(size_t)NPAD * DD];
__device__ __align__(16) __nv_bfloat16 g_hh[(size_t)NPAD * DD];
__device__ __align__(16) __nv_bfloat16 g_hl[(size_t)NPAD * DD];
__device__ __align__(16) __nv_bfloat16 g_aggh[(size_t)NPAD * DD];
__device__ __align__(16) __nv_bfloat16 g_aggl[(size_t)NPAD * DD];
__device__ __align__(16) __half        g_xf16[(size_t)NPAD * DD];  // gather source L1
__device__ __align__(16) __half        g_hf16[(size_t)NPAD * DD];  // gather source L2
__device__ __align__(16) __nv_bfloat16 g_wpack[8 * 128 * 128];     // row-major W slots
__device__ int g_srcs[NE];
__device__ int g_rp[NN + 1];
__device__ int g_pos[NN];
__device__ int g_cnt[NN];
__device__ int g_bs[128];
__device__ int g_is64;

// ---------------------------------------------------------------------------
// helpers
// ---------------------------------------------------------------------------
__device__ __forceinline__ uint32_t smem_to_u32(const void* p) {
    uint32_t a;
    asm("{ .reg .u64 t; cvta.to.shared.u64 t, %1; cvt.u32.u64 %0, t; }"
        : "=r"(a) : "l"(p));
    return a;
}
__device__ __forceinline__ unsigned short bfu(__nv_bfloat16 b) { return __bfloat16_as_ushort(b); }
__device__ __forceinline__ void split2(float a, float b, unsigned& hi, unsigned& lo) {
    __nv_bfloat16 ah = __float2bfloat16(a), bh = __float2bfloat16(b);
    float ar = a - __bfloat162float(ah), br = b - __bfloat162float(bh);
    __nv_bfloat16 al = __float2bfloat16(ar), bl = __float2bfloat16(br);
    hi = (unsigned)bfu(ah) | ((unsigned)bfu(bh) << 16);
    lo = (unsigned)bfu(al) | ((unsigned)bfu(bl) << 16);
}
__device__ __forceinline__ void cp_async16(uint32_t saddr, const void* gptr) {
    asm volatile("cp.async.cg.shared.global [%0], [%1], 16;"
                 :: "r"(saddr), "l"(gptr));
}
#define CP_COMMIT() asm volatile("cp.async.commit_group;" ::: "memory")
#define CP_WAIT1()  asm volatile("cp.async.wait_group 1;" ::: "memory")
#define CP_WAIT0()  asm volatile("cp.async.wait_group 0;" ::: "memory")

// ---------------------------------------------------------------------------
// int64/int32 edge dtype detection
// ---------------------------------------------------------------------------
__global__ void detect_kernel(const unsigned int* __restrict__ ebuf) {
    __shared__ int nz;
    if (threadIdx.x == 0) nz = 0;
    __syncthreads();
    for (int i = threadIdx.x; i < 8192; i += blockDim.x)
        if (ebuf[2 * i + 1] != 0u) nz = 1;
    __syncthreads();
    if (threadIdx.x == 0) g_is64 = (nz == 0) ? 1 : 0;
}

__global__ void zero_int_kernel(int4* __restrict__ p, int n4) {
    int i = blockIdx.x * blockDim.x + threadIdx.x;
    const int stride = gridDim.x * blockDim.x;
    const int4 z = make_int4(0, 0, 0, 0);
    for (; i < n4; i += stride) p[i] = z;
}

// ---------------------------------------------------------------------------
// CSR build: histogram -> scan -> fill
// ---------------------------------------------------------------------------
__global__ void hist_kernel(const void* __restrict__ edges, int* __restrict__ cnt) {
    const int is64 = g_is64;
    const long long* e64 = (const long long*)edges;
    const int*       e32 = (const int*)edges;
    int i = blockIdx.x * blockDim.x + threadIdx.x;
    const int stride = gridDim.x * blockDim.x;
    for (; i < NE; i += stride) {
        int dst = is64 ? (int)e64[NE + i] : e32[NE + i];
        atomicAdd(&cnt[dst], 1);
    }
}

__global__ void scan1_kernel(const int* __restrict__ cnt, int* __restrict__ rp,
                             int* __restrict__ bs) {
    __shared__ int wsum[8];
    const int t = threadIdx.x, lane = t & 31, w = t >> 5;
    const int base = blockIdx.x * 1024 + t * 4;
    int v0 = (base + 0 < NN) ? cnt[base + 0] : 0;
    int v1 = (base + 1 < NN) ? cnt[base + 1] : 0;
    int v2 = (base + 2 < NN) ? cnt[base + 2] : 0;
    int v3 = (base + 3 < NN) ? cnt[base + 3] : 0;
    const int tot = v0 + v1 + v2 + v3;
    int inc = tot;
#pragma unroll
    for (int off = 1; off < 32; off <<= 1) {
        int n = __shfl_up_sync(0xffffffff, inc, off);
        if (lane >= off) inc += n;
    }
    if (lane == 31) wsum[w] = inc;
    __syncthreads();
    if (w == 0) {
        int s = (lane < 8) ? wsum[lane] : 0;
#pragma unroll
        for (int off = 1; off < 8; off <<= 1) {
            int n = __shfl_up_sync(0xffffffff, s, off);
            if (lane >= off) s += n;
        }
        if (lane < 8) wsum[lane] = s;
    }
    __syncthreads();
    const int wbase = (w > 0) ? wsum[w - 1] : 0;
    const int exc = wbase + inc - tot;
    if (base + 0 < NN) rp[base + 0] = exc;
    if (base + 1 < NN) rp[base + 1] = exc + v0;
    if (base + 2 < NN) rp[base + 2] = exc + v0 + v1;
    if (base + 3 < NN) rp[base + 3] = exc + v0 + v1 + v2;
    if (t == 255) bs[blockIdx.x] = wbase + inc;
}

__global__ void scan2_kernel(int* __restrict__ bs) {
    __shared__ int ws[4];
    const int t = threadIdx.x, lane = t & 31, w = t >> 5;
    int v = (t < NB_SCAN) ? bs[t] : 0;
    int inc = v;
#pragma unroll
    for (int off = 1; off < 32; off <<= 1) {
        int n = __shfl_up_sync(0xffffffff, inc, off);
        if (lane >= off) inc += n;
    }
    if (lane == 31) ws[w] = inc;
    __syncthreads();
    if (w == 0 && lane < 4) {
        int s = ws[lane];
#pragma unroll
        for (int off = 1; off < 4; off <<= 1) {
            int n = __shfl_up_sync(0x0000000f, s, off);
            if (lane >= off) s += n;
        }
        ws[lane] = s;
    }
    __syncthreads();
    const int wbase = (w > 0) ? ws[w - 1] : 0;
    if (t < NB_SCAN) bs[t] = wbase + inc - v;
}

__global__ void scan3_kernel(int* __restrict__ rp, int* __restrict__ pos,
                             const int* __restrict__ bs) {
    const int i = blockIdx.x * blockDim.x + threadIdx.x;
    if (i < NN) {
        const int v = rp[i] + bs[i >> 10];
        rp[i] = v;
        pos[i] = v;
    }
    if (i == 0) rp[NN] = NE;
}

__global__ void fill_kernel(const void* __restrict__ edges, int* __restrict__ pos,
                            int* __restrict__ srcs) {
    const int is64 = g_is64;
    const long long* e64 = (const long long*)edges;
    const int*       e32 = (const int*)edges;
    int i = blockIdx.x * blockDim.x + threadIdx.x;
    const int stride = gridDim.x * blockDim.x;
    for (; i < NE; i += stride) {
        int src, dst;
        if (is64) { src = (int)e64[i]; dst = (int)e64[NE + i]; }
        else      { src = e32[i];      dst = e32[NE + i]; }
        const int p = atomicAdd(&pos[dst], 1);
        srcs[p] = src;
    }
}

// ---------------------------------------------------------------------------
// x -> (xh, xl) bf16 split + fp16 copy for the gather
// ---------------------------------------------------------------------------
__global__ void convert_x_kernel(const float4* __restrict__ x,
                                 __nv_bfloat16* __restrict__ xh,
                                 __nv_bfloat16* __restrict__ xl,
                                 __half* __restrict__ xf) {
    const int id = blockIdx.x * blockDim.x + threadIdx.x;
    const int row = id >> 5, lane = id & 31;
    if (row >= NN) return;
    float4 v = x[(size_t)row * 32 + lane];
    unsigned h0, l0, h1, l1;
    split2(v.x, v.y, h0, l0);
    split2(v.z, v.w, h1, l1);
    *(uint2*)(xh + (size_t)row * DD + lane * 4) = make_uint2(h0, h1);
    *(uint2*)(xl + (size_t)row * DD + lane * 4) = make_uint2(l0, l1);
    __half2 f0 = __floats2half2_rn(v.x, v.y);
    __half2 f1 = __floats2half2_rn(v.z, v.w);
    *(__half2*)(xf + (size_t)row * DD + lane * 4 + 0) = f0;
    *(__half2*)(xf + (size_t)row * DD + lane * 4 + 2) = f1;
}

// ---------------------------------------------------------------------------
// Weight prep: W fp32 [j][k] -> bf16 hi/lo, plain row-major slots.
// Slots: L1: 0=Wl_h, 1=Wr_h, 2=Wl_l, 3=Wr_l; L2: 4-7 same order.
// ---------------------------------------------------------------------------
__global__ void prep_w_kernel(const float* __restrict__ Wl1, const float* __restrict__ Wr1,
                              const float* __restrict__ Wl2, const float* __restrict__ Wr2,
                              __nv_bfloat16* __restrict__ wpack) {
    const int id = blockIdx.x * blockDim.x + threadIdx.x;  // 0..8191
    if (id >= 8192) return;
    const int tIdx = id >> 11;
    const int rem = id & 2047;
    const int j = rem >> 4, cu = rem & 15;
    const float* W = (tIdx == 0) ? Wl1 : (tIdx == 1) ? Wr1 : (tIdx == 2) ? Wl2 : Wr2;
    const float4* p = (const float4*)(W + (size_t)j * DD + cu * 8);
    float4 v0 = p[0], v1 = p[1];
    unsigned hs[4], ls[4];
    split2(v0.x, v0.y, hs[0], ls[0]);
    split2(v0.z, v0.w, hs[1], ls[1]);
    split2(v1.x, v1.y, hs[2], ls[2]);
    split2(v1.z, v1.w, hs[3], ls[3]);
    const int hslot = (tIdx >> 1) * 4 + (tIdx & 1);
    const int lslot = hslot + 2;
    const size_t off = (size_t)j * DD + cu * 8;
    *(uint4*)(wpack + (size_t)hslot * 16384 + off) = make_uint4(hs[0], hs[1], hs[2], hs[3]);
    *(uint4*)(wpack + (size_t)lslot * 16384 + off) = make_uint4(ls[0], ls[1], ls[2], ls[3]);
}

// ---------------------------------------------------------------------------
// Gather (fp16 source): warp per dst node -> fp32 mean -> bf16 hi/lo.
// 256B/edge instead of 512B -> half the LTS traffic of the fp32 gather.
// ---------------------------------------------------------------------------
__global__ void gather_f16_kernel(const __half* __restrict__ xin,
                                  const int* __restrict__ rp,
                                  const int* __restrict__ srcs,
                                  __nv_bfloat16* __restrict__ aggh,
                                  __nv_bfloat16* __restrict__ aggl) {
    const int warp = (blockIdx.x * blockDim.x + threadIdx.x) >> 5;
    const int lane = threadIdx.x & 31;
    if (warp >= NN) return;
    const int s = rp[warp], e = rp[warp + 1];
    float4 acc = make_float4(0.f, 0.f, 0.f, 0.f);
    int i = s;
    for (; i + 1 < e; i += 2) {
        const uint2 u0 = __ldg((const uint2*)(xin + (size_t)srcs[i]     * DD + lane * 4));
        const uint2 u1 = __ldg((const uint2*)(xin + (size_t)srcs[i + 1] * DD + lane * 4));
        float2 a0 = __half22float2(*(const __half2*)&u0.x);
        float2 a1 = __half22float2(*(const __half2*)&u0.y);
        float2 b0 = __half22float2(*(const __half2*)&u1.x);
        float2 b1 = __half22float2(*(const __half2*)&u1.y);
        acc.x += a0.x + b0.x; acc.y += a0.y + b0.y;
        acc.z += a1.x + b1.x; acc.w += a1.y + b1.y;
    }
    if (i < e) {
        const uint2 u = __ldg((const uint2*)(xin + (size_t)srcs[i] * DD + lane * 4));
        float2 a0 = __half22float2(*(const __half2*)&u.x);
        float2 a1 = __half22float2(*(const __half2*)&u.y);
        acc.x += a0.x; acc.y += a0.y; acc.z += a1.x; acc.w += a1.y;
    }
    const float inv = 1.0f / fmaxf((float)(e - s), 1.0f);
    acc.x *= inv; acc.y *= inv; acc.z *= inv; acc.w *= inv;
    unsigned h0, l0, h1, l1;
    split2(acc.x, acc.y, h0, l0);
    split2(acc.z, acc.w, h1, l1);
    *(uint2*)(aggh + (size_t)warp * DD + lane * 4) = make_uint2(h0, h1);
    *(uint2*)(aggl + (size_t)warp * DD + lane * 4) = make_uint2(l0, l1);
}

// ---------------------------------------------------------------------------
// mma.sync (HMMA) node GEMM, cp.async double-buffered, A-reuse schedule.
// out = [agg|x] @ [Wl;Wr]^T + bias, split-bf16 3-term => 12 MMA chunks K=64.
// ---------------------------------------------------------------------------
#define PADB 144
#define ACH  (128 * PADB)          // 18432 bytes per buffer
#define NODE_SMEM (4 * ACH)        // 73728

__global__ void __launch_bounds__(256, 2)
node_mma_kernel(const __nv_bfloat16* __restrict__ a0,   // agg_h
                const __nv_bfloat16* __restrict__ a1,   // x_h / h_h
                const __nv_bfloat16* __restrict__ a2,   // agg_l
                const __nv_bfloat16* __restrict__ a3,   // x_l / h_l
                const __nv_bfloat16* __restrict__ wpack,  // layer's 4 slots
                const float* __restrict__ bias,
                float* __restrict__ outf,
                __nv_bfloat16* __restrict__ oh,
                __nv_bfloat16* __restrict__ ol,
                __half* __restrict__ of,
                int relu_split)
{
    extern __shared__ char smem[];
    const uint32_t uS = smem_to_u32(smem);

    const int tid  = threadIdx.x;
    const int wid  = tid >> 5;
    const int lane = tid & 31;
    const int wm   = wid >> 2;          // 0..1
    const int wn   = wid & 3;           // 0..3
    const int row0 = blockIdx.x << 7;

    // chunk schedule (A-reuse pairs first, then Al*Bh term)
    const int aSrcT[12] = {0,0,0,0, 1,1,1,1, 2,2,3,3};
    const int aKoT [12] = {0,0,64,64, 0,0,64,64, 0,64,0,64};
    const int aNewT[12] = {1,0,1,0, 1,0,1,0, 1,1,1,1};
    const int aBufT[12] = {0,0,1,1, 0,0,1,1, 0,1,0,1};
    const int bSlotT[12]= {0,2,0,2, 1,3,1,3, 0,0,1,1};
    const int bKoT [12] = {0,0,64,64, 0,0,64,64, 0,64,0,64};
    const int bBufT[12] = {0,1,0,1, 0,1,0,1, 0,1,0,1};

    const __nv_bfloat16* aBase[4] = {a0, a1, a2, a3};

    const int a_row = wm * 64 + (lane & 15);
    const int a_kb  = ((lane >> 4) & 1) << 4;
    const int b_row = wn * 32 + (lane & 7);
    const int b_kb  = ((lane >> 3) & 1) << 4;

    float acc[4][4][4];
#pragma unroll
    for (int mt = 0; mt < 4; ++mt)
#pragma unroll
        for (int nt = 0; nt < 4; ++nt)
#pragma unroll
            for (int q = 0; q < 4; ++q) acc[mt][nt][q] = 0.f;

    // ---- issue chunk-0 loads ----
    {
        const __nv_bfloat16* As = aBase[aSrcT[0]] + (size_t)row0 * DD + aKoT[0];
        const __nv_bfloat16* Bs = wpack + (size_t)bSlotT[0] * 16384 + bKoT[0];
#pragma unroll
        for (int i = 0; i < 4; ++i) {
            const int u = i * 256 + tid;
            const int r = u >> 3, g = u & 7;
            cp_async16(uS + 0 * ACH + r * PADB + g * 16, As + (size_t)r * DD + g * 8);
        }
#pragma unroll
        for (int i = 0; i < 4; ++i) {
            const int u = i * 256 + tid;
            const int r = u >> 3, g = u & 7;
            cp_async16(uS + 2 * ACH + r * PADB + g * 16, Bs + (size_t)r * DD + g * 8);
        }
        CP_COMMIT();
    }

#pragma unroll
    for (int c = 0; c < 12; ++c) {
        __syncthreads();

        if (c < 11) {
            const int n = c + 1;
            if (aNewT[n]) {
                const __nv_bfloat16* As = aBase[aSrcT[n]] + (size_t)row0 * DD + aKoT[n];
                const uint32_t dst = uS + aBufT[n] * ACH;
#pragma unroll
                for (int i = 0; i < 4; ++i) {
                    const int u = i * 256 + tid;
                    const int r = u >> 3, g = u & 7;
                    cp_async16(dst + r * PADB + g * 16, As + (size_t)r * DD + g * 8);
                }
            }
            {
                const __nv_bfloat16* Bs = wpack + (size_t)bSlotT[n] * 16384 + bKoT[n];
                const uint32_t dst = uS + 2 * ACH + bBufT[n] * ACH;
#pragma unroll
                for (int i = 0; i < 4; ++i) {
                    const int u = i * 256 + tid;
                    const int r = u >> 3, g = u & 7;
                    cp_async16(dst + r * PADB + g * 16, Bs + (size_t)r * DD + g * 8);
                }
            }
            CP_COMMIT();
            CP_WAIT1();
        } else {
            CP_WAIT0();
        }
        __syncthreads();

        const uint32_t uA = uS + aBufT[c] * ACH;
        const uint32_t uB = uS + 2 * ACH + bBufT[c] * ACH;

#pragma unroll
        for (int ks = 0; ks < 4; ++ks) {
            uint32_t af[4][4];
#pragma unroll
            for (int mt = 0; mt < 4; ++mt) {
                const uint32_t addr = uA + (a_row + mt * 16) * PADB + ks * 32 + a_kb;
                asm volatile("ldmatrix.sync.aligned.m8n8.x4.shared.b16 {%0,%1,%2,%3}, [%4];"
                             : "=r"(af[mt][0]), "=r"(af[mt][1]),
                               "=r"(af[mt][2]), "=r"(af[mt][3])
                             : "r"(addr));
            }
            uint32_t bfr[4][2];
#pragma unroll
            for (int nt = 0; nt < 4; ++nt) {
                const uint32_t addr = uB + (b_row + nt * 8) * PADB + ks * 32 + b_kb;
                asm volatile("ldmatrix.sync.aligned.m8n8.x2.shared.b16 {%0,%1}, [%2];"
                             : "=r"(bfr[nt][0]), "=r"(bfr[nt][1])
                             : "r"(addr));
            }
#pragma unroll
            for (int mt = 0; mt < 4; ++mt)
#pragma unroll
                for (int nt = 0; nt < 4; ++nt) {
                    asm volatile(
                        "mma.sync.aligned.m16n8k16.row.col.f32.bf16.bf16.f32 "
                        "{%0,%1,%2,%3}, {%4,%5,%6,%7}, {%8,%9}, {%0,%1,%2,%3};"
                        : "+f"(acc[mt][nt][0]), "+f"(acc[mt][nt][1]),
                          "+f"(acc[mt][nt][2]), "+f"(acc[mt][nt][3])
                        : "r"(af[mt][0]), "r"(af[mt][1]),
                          "r"(af[mt][2]), "r"(af[mt][3]),
                          "r"(bfr[nt][0]), "r"(bfr[nt][1]));
                }
        }
    }

    // ---- epilogue ----
    const int col_base = wn * 32 + ((lane & 3) << 1);
    float bv[4][2];
#pragma unroll
    for (int nt = 0; nt < 4; ++nt) {
        bv[nt][0] = __ldg(bias + col_base + nt * 8);
        bv[nt][1] = __ldg(bias + col_base + nt * 8 + 1);
    }

#pragma unroll
    for (int mt = 0; mt < 4; ++mt) {
        const int r0 = row0 + wm * 64 + mt * 16 + (lane >> 2);
        const int r1 = r0 + 8;
#pragma unroll
        for (int nt = 0; nt < 4; ++nt) {
            const int col = col_base + nt * 8;
            float v0 = acc[mt][nt][0] + bv[nt][0];
            float v1 = acc[mt][nt][1] + bv[nt][1];
            float v2 = acc[mt][nt][2] + bv[nt][0];
            float v3 = acc[mt][nt][3] + bv[nt][1];
            if (relu_split) {
                v0 = fmaxf(v0, 0.f); v1 = fmaxf(v1, 0.f);
                v2 = fmaxf(v2, 0.f); v3 = fmaxf(v3, 0.f);
                unsigned h01, l01, h23, l23;
                split2(v0, v1, h01, l01);
                split2(v2, v3, h23, l23);
                if (r0 < NN) {
                    *(unsigned*)(oh + (size_t)r0 * DD + col) = h01;
                    *(unsigned*)(ol + (size_t)r0 * DD + col) = l01;
                    *(__half2*)(of + (size_t)r0 * DD + col) = __floats2half2_rn(v0, v1);
                }
                if (r1 < NN) {
                    *(unsigned*)(oh + (size_t)r1 * DD + col) = h23;
                    *(unsigned*)(ol + (size_t)r1 * DD + col) = l23;
                    *(__half2*)(of + (size_t)r1 * DD + col) = __floats2half2_rn(v2, v3);
                }
            } else {
                if (r0 < NN) *(float2*)(outf + (size_t)r0 * DD + col) = make_float2(v0, v1);
                if (r1 < NN) *(float2*)(outf + (size_t)r1 * DD + col) = make_float2(v2, v3);
            }
        }
    }
}

// ---------------------------------------------------------------------------
// Launch sequence (default stream, graph-capturable, allocation-free)
// ---------------------------------------------------------------------------
extern "C" void kernel_launch(void* const* d_in, const int* in_sizes, int n_in,
                              void* d_out, int out_size)
{
    const float* x   = (const float*)d_in[0];
    const void*  ei  = d_in[1];
    const float* W1l = (const float*)d_in[2];
    const float* b1  = (const float*)d_in[3];
    const float* W1r = (const float*)d_in[4];
    const float* W2l = (const float*)d_in[5];
    const float* b2  = (const float*)d_in[6];
    const float* W2r = (const float*)d_in[7];
    float* out = (float*)d_out;

    __nv_bfloat16 *xh, *xl, *hh, *hl, *aggh, *aggl, *wpack;
    __half *xf16, *hf16;
    int *srcs, *rp, *pos, *cnt, *bs;
    cudaGetSymbolAddress((void**)&xh,    g_xh);
    cudaGetSymbolAddress((void**)&xl,    g_xl);
    cudaGetSymbolAddress((void**)&hh,    g_hh);
    cudaGetSymbolAddress((void**)&hl,    g_hl);
    cudaGetSymbolAddress((void**)&aggh,  g_aggh);
    cudaGetSymbolAddress((void**)&aggl,  g_aggl);
    cudaGetSymbolAddress((void**)&xf16,  g_xf16);
    cudaGetSymbolAddress((void**)&hf16,  g_hf16);
    cudaGetSymbolAddress((void**)&wpack, g_wpack);
    cudaGetSymbolAddress((void**)&srcs,  g_srcs);
    cudaGetSymbolAddress((void**)&rp,    g_rp);
    cudaGetSymbolAddress((void**)&pos,   g_pos);
    cudaGetSymbolAddress((void**)&cnt,   g_cnt);
    cudaGetSymbolAddress((void**)&bs,    g_bs);

    cudaFuncSetAttribute(node_mma_kernel,
                         cudaFuncAttributeMaxDynamicSharedMemorySize, NODE_SMEM);

    detect_kernel<<<1, 256>>>((const unsigned int*)ei);

    // CSR build
    zero_int_kernel<<<64, 256>>>((int4*)cnt, NN / 4);
    hist_kernel<<<2048, 256>>>(ei, cnt);
    scan1_kernel<<<NB_SCAN, 256>>>(cnt, rp, bs);
    scan2_kernel<<<1, 128>>>(bs);
    scan3_kernel<<<(NN + 255) / 256, 256>>>(rp, pos, bs);
    fill_kernel<<<2048, 256>>>(ei, pos, srcs);

    // bf16 split + fp16 copy / weight packing
    convert_x_kernel<<<(NN * 32 + 255) / 256, 256>>>((const float4*)x, xh, xl, xf16);
    prep_w_kernel<<<32, 256>>>(W1l, W1r, W2l, W2r, wpack);

    // Layer 1
    gather_f16_kernel<<<(NN * 32 + 255) / 256, 256>>>(xf16, rp, srcs, aggh, aggl);
    node_mma_kernel<<<NTILE, 256, NODE_SMEM>>>(aggh, xh, aggl, xl,
                                               wpack, b1, nullptr, hh, hl, hf16, 1);

    // Layer 2
    gather_f16_kernel<<<(NN * 32 + 255) / 256, 256>>>(hf16, rp, srcs, aggh, aggl);
    node_mma_kernel<<<NTILE, 256, NODE_SMEM>>>(aggh, hh, aggl, hl,
                                               wpack + 4 * 16384, b2, out, nullptr, nullptr, nullptr, 0);
}

// round 12
// speedup vs baseline: 3.5221x; 1.4658x over previous
#include <cuda_runtime.h>
#include <cuda_fp16.h>
#include <cstdint>
#include <cstddef>

#define NN 100000
#define NE 1600000
#define DD 128
#define NPAD 100096          // 782 * 128
#define NTILE 782
#define NB_SCAN 98           // ceil(100000 / 1024)

// ---------------------------------------------------------------------------
// Device scratch (no allocation allowed)
// ---------------------------------------------------------------------------
__device__ __align__(16) __half g_xf[(size_t)NPAD * DD];    // x as fp16
__device__ __align__(16) __half g_hf[(size_t)NPAD * DD];    // h as fp16
__device__ __align__(16) __half g_aggf[(size_t)NPAD * DD];  // aggregated mean fp16
__device__ __align__(16) __half g_wpack[4 * 128 * 128];     // Wl1,Wr1,Wl2,Wr2 fp16
__device__ int g_srcs[NE];
__device__ int g_rp[NN + 1];
__device__ int g_pos[NN];
__device__ int g_cnt[NN];
__device__ int g_bs[128];
__device__ int g_is64;

// ---------------------------------------------------------------------------
// helpers
// ---------------------------------------------------------------------------
__device__ __forceinline__ uint32_t smem_to_u32(const void* p) {
    uint32_t a;
    asm("{ .reg .u64 t; cvta.to.shared.u64 t, %1; cvt.u32.u64 %0, t; }"
        : "=r"(a) : "l"(p));
    return a;
}
__device__ __forceinline__ void cp_async16(uint32_t saddr, const void* gptr) {
    asm volatile("cp.async.cg.shared.global [%0], [%1], 16;"
                 :: "r"(saddr), "l"(gptr));
}
#define CP_COMMIT() asm volatile("cp.async.commit_group;" ::: "memory")
#define CP_WAIT1()  asm volatile("cp.async.wait_group 1;" ::: "memory")
#define CP_WAIT0()  asm volatile("cp.async.wait_group 0;" ::: "memory")

// ---------------------------------------------------------------------------
// int64/int32 edge dtype detection
// ---------------------------------------------------------------------------
__global__ void detect_kernel(const unsigned int* __restrict__ ebuf) {
    __shared__ int nz;
    if (threadIdx.x == 0) nz = 0;
    __syncthreads();
    for (int i = threadIdx.x; i < 8192; i += blockDim.x)
        if (ebuf[2 * i + 1] != 0u) nz = 1;
    __syncthreads();
    if (threadIdx.x == 0) g_is64 = (nz == 0) ? 1 : 0;
}

__global__ void zero_int_kernel(int4* __restrict__ p, int n4) {
    int i = blockIdx.x * blockDim.x + threadIdx.x;
    const int stride = gridDim.x * blockDim.x;
    const int4 z = make_int4(0, 0, 0, 0);
    for (; i < n4; i += stride) p[i] = z;
}

// ---------------------------------------------------------------------------
// CSR build: histogram -> scan -> fill
// ---------------------------------------------------------------------------
__global__ void hist_kernel(const void* __restrict__ edges, int* __restrict__ cnt) {
    const int is64 = g_is64;
    const long long* e64 = (const long long*)edges;
    const int*       e32 = (const int*)edges;
    int i = blockIdx.x * blockDim.x + threadIdx.x;
    const int stride = gridDim.x * blockDim.x;
    for (; i < NE; i += stride) {
        int dst = is64 ? (int)e64[NE + i] : e32[NE + i];
        atomicAdd(&cnt[dst], 1);
    }
}

__global__ void scan1_kernel(const int* __restrict__ cnt, int* __restrict__ rp,
                             int* __restrict__ bs) {
    __shared__ int wsum[8];
    const int t = threadIdx.x, lane = t & 31, w = t >> 5;
    const int base = blockIdx.x * 1024 + t * 4;
    int v0 = (base + 0 < NN) ? cnt[base + 0] : 0;
    int v1 = (base + 1 < NN) ? cnt[base + 1] : 0;
    int v2 = (base + 2 < NN) ? cnt[base + 2] : 0;
    int v3 = (base + 3 < NN) ? cnt[base + 3] : 0;
    const int tot = v0 + v1 + v2 + v3;
    int inc = tot;
#pragma unroll
    for (int off = 1; off < 32; off <<= 1) {
        int n = __shfl_up_sync(0xffffffff, inc, off);
        if (lane >= off) inc += n;
    }
    if (lane == 31) wsum[w] = inc;
    __syncthreads();
    if (w == 0) {
        int s = (lane < 8) ? wsum[lane] : 0;
#pragma unroll
        for (int off = 1; off < 8; off <<= 1) {
            int n = __shfl_up_sync(0xffffffff, s, off);
            if (lane >= off) s += n;
        }
        if (lane < 8) wsum[lane] = s;
    }
    __syncthreads();
    const int wbase = (w > 0) ? wsum[w - 1] : 0;
    const int exc = wbase + inc - tot;
    if (base + 0 < NN) rp[base + 0] = exc;
    if (base + 1 < NN) rp[base + 1] = exc + v0;
    if (base + 2 < NN) rp[base + 2] = exc + v0 + v1;
    if (base + 3 < NN) rp[base + 3] = exc + v0 + v1 + v2;
    if (t == 255) bs[blockIdx.x] = wbase + inc;
}

__global__ void scan2_kernel(int* __restrict__ bs) {
    __shared__ int ws[4];
    const int t = threadIdx.x, lane = t & 31, w = t >> 5;
    int v = (t < NB_SCAN) ? bs[t] : 0;
    int inc = v;
#pragma unroll
    for (int off = 1; off < 32; off <<= 1) {
        int n = __shfl_up_sync(0xffffffff, inc, off);
        if (lane >= off) inc += n;
    }
    if (lane == 31) ws[w] = inc;
    __syncthreads();
    if (w == 0 && lane < 4) {
        int s = ws[lane];
#pragma unroll
        for (int off = 1; off < 4; off <<= 1) {
            int n = __shfl_up_sync(0x0000000f, s, off);
            if (lane >= off) s += n;
        }
        ws[lane] = s;
    }
    __syncthreads();
    const int wbase = (w > 0) ? ws[w - 1] : 0;
    if (t < NB_SCAN) bs[t] = wbase + inc - v;
}

__global__ void scan3_kernel(int* __restrict__ rp, int* __restrict__ pos,
                             const int* __restrict__ bs) {
    const int i = blockIdx.x * blockDim.x + threadIdx.x;
    if (i < NN) {
        const int v = rp[i] + bs[i >> 10];
        rp[i] = v;
        pos[i] = v;
    }
    if (i == 0) rp[NN] = NE;
}

__global__ void fill_kernel(const void* __restrict__ edges, int* __restrict__ pos,
                            int* __restrict__ srcs) {
    const int is64 = g_is64;
    const long long* e64 = (const long long*)edges;
    const int*       e32 = (const int*)edges;
    int i = blockIdx.x * blockDim.x + threadIdx.x;
    const int stride = gridDim.x * blockDim.x;
    for (; i < NE; i += stride) {
        int src, dst;
        if (is64) { src = (int)e64[i]; dst = (int)e64[NE + i]; }
        else      { src = e32[i];      dst = e32[NE + i]; }
        const int p = atomicAdd(&pos[dst], 1);
        srcs[p] = src;
    }
}

// ---------------------------------------------------------------------------
// x (fp32) -> fp16
// ---------------------------------------------------------------------------
__global__ void convert_x_kernel(const float4* __restrict__ x,
                                 __half* __restrict__ xf) {
    const int id = blockIdx.x * blockDim.x + threadIdx.x;
    const int row = id >> 5, lane = id & 31;
    if (row >= NN) return;
    float4 v = x[(size_t)row * 32 + lane];
    __half2 f0 = __floats2half2_rn(v.x, v.y);
    __half2 f1 = __floats2half2_rn(v.z, v.w);
    *(__half2*)(xf + (size_t)row * DD + lane * 4 + 0) = f0;
    *(__half2*)(xf + (size_t)row * DD + lane * 4 + 2) = f1;
}

// ---------------------------------------------------------------------------
// Weight prep: 4 matrices fp32 -> fp16 row-major slots (Wl1, Wr1, Wl2, Wr2)
// ---------------------------------------------------------------------------
__global__ void prep_w_kernel(const float* __restrict__ Wl1, const float* __restrict__ Wr1,
                              const float* __restrict__ Wl2, const float* __restrict__ Wr2,
                              __half* __restrict__ wpack) {
    const int id = blockIdx.x * blockDim.x + threadIdx.x;  // 0..8191
    if (id >= 8192) return;
    const int tIdx = id >> 11;
    const int rem = id & 2047;
    const int j = rem >> 4, cu = rem & 15;
    const float* W = (tIdx == 0) ? Wl1 : (tIdx == 1) ? Wr1 : (tIdx == 2) ? Wl2 : Wr2;
    const float4* p = (const float4*)(W + (size_t)j * DD + cu * 8);
    float4 v0 = p[0], v1 = p[1];
    __half2 h0 = __floats2half2_rn(v0.x, v0.y);
    __half2 h1 = __floats2half2_rn(v0.z, v0.w);
    __half2 h2 = __floats2half2_rn(v1.x, v1.y);
    __half2 h3 = __floats2half2_rn(v1.z, v1.w);
    __half* dst = wpack + (size_t)tIdx * 16384 + (size_t)j * DD + cu * 8;
    *(uint4*)dst = make_uint4(*(unsigned*)&h0, *(unsigned*)&h1,
                              *(unsigned*)&h2, *(unsigned*)&h3);
}

// ---------------------------------------------------------------------------
// Gather (fp16 source): warp per dst node -> fp32 mean -> fp16 out
// ---------------------------------------------------------------------------
__global__ void gather_f16_kernel(const __half* __restrict__ xin,
                                  const int* __restrict__ rp,
                                  const int* __restrict__ srcs,
                                  __half* __restrict__ aggf) {
    const int warp = (blockIdx.x * blockDim.x + threadIdx.x) >> 5;
    const int lane = threadIdx.x & 31;
    if (warp >= NN) return;
    const int s = rp[warp], e = rp[warp + 1];
    float4 acc = make_float4(0.f, 0.f, 0.f, 0.f);
    int i = s;
    for (; i + 1 < e; i += 2) {
        const uint2 u0 = __ldg((const uint2*)(xin + (size_t)srcs[i]     * DD + lane * 4));
        const uint2 u1 = __ldg((const uint2*)(xin + (size_t)srcs[i + 1] * DD + lane * 4));
        float2 a0 = __half22float2(*(const __half2*)&u0.x);
        float2 a1 = __half22float2(*(const __half2*)&u0.y);
        float2 b0 = __half22float2(*(const __half2*)&u1.x);
        float2 b1 = __half22float2(*(const __half2*)&u1.y);
        acc.x += a0.x + b0.x; acc.y += a0.y + b0.y;
        acc.z += a1.x + b1.x; acc.w += a1.y + b1.y;
    }
    if (i < e) {
        const uint2 u = __ldg((const uint2*)(xin + (size_t)srcs[i] * DD + lane * 4));
        float2 a0 = __half22float2(*(const __half2*)&u.x);
        float2 a1 = __half22float2(*(const __half2*)&u.y);
        acc.x += a0.x; acc.y += a0.y; acc.z += a1.x; acc.w += a1.y;
    }
    const float inv = 1.0f / fmaxf((float)(e - s), 1.0f);
    __half2 o0 = __floats2half2_rn(acc.x * inv, acc.y * inv);
    __half2 o1 = __floats2half2_rn(acc.z * inv, acc.w * inv);
    *(uint2*)(aggf + (size_t)warp * DD + lane * 4) =
        make_uint2(*(unsigned*)&o0, *(unsigned*)&o1);
}

// ---------------------------------------------------------------------------
// fp16 mma.sync node GEMM, cp.async double-buffered.
// out = [agg|x] @ [Wl;Wr]^T + bias ; 4 chunks of K=64 (single term).
// CTA: 128x128 C; 8 warps 2x4, each 64x32; SMEM rows padded to 144B.
// ---------------------------------------------------------------------------
#define PADB 144
#define ACH  (128 * PADB)          // 18432 bytes per buffer
#define NODE_SMEM (4 * ACH)        // 73728

__global__ void __launch_bounds__(256, 2)
node_mma_kernel(const __half* __restrict__ aggf,
                const __half* __restrict__ xf,    // x or h
                const __half* __restrict__ w,     // layer slots: +0 Wl, +16384 Wr
                const float* __restrict__ bias,
                float* __restrict__ outf,
                __half* __restrict__ of16,
                int relu_split)
{
    extern __shared__ char smem[];
    const uint32_t uS = smem_to_u32(smem);

    const int tid  = threadIdx.x;
    const int wid  = tid >> 5;
    const int lane = tid & 31;
    const int wm   = wid >> 2;          // 0..1
    const int wn   = wid & 3;           // 0..3
    const int row0 = blockIdx.x << 7;

    // 4 chunks: {agg,k0},{agg,k64},{x,k0},{x,k64} ; B: Wl/Wl/Wr/Wr
    const int aSrcT[4] = {0, 0, 1, 1};
    const int aKoT [4] = {0, 64, 0, 64};
    const int bSlT [4] = {0, 0, 1, 1};
    const int bKoT [4] = {0, 64, 0, 64};
    const __half* aBase[2] = {aggf, xf};

    const int a_row = wm * 64 + (lane & 15);
    const int a_kb  = ((lane >> 4) & 1) << 4;
    const int b_row = wn * 32 + (lane & 7);
    const int b_kb  = ((lane >> 3) & 1) << 4;

    float acc[4][4][4];
#pragma unroll
    for (int mt = 0; mt < 4; ++mt)
#pragma unroll
        for (int nt = 0; nt < 4; ++nt)
#pragma unroll
            for (int q = 0; q < 4; ++q) acc[mt][nt][q] = 0.f;

    // ---- issue chunk-0 loads ----
    {
        const __half* As = aBase[0] + (size_t)row0 * DD;
        const __half* Bs = w;
#pragma unroll
        for (int i = 0; i < 4; ++i) {
            const int u = i * 256 + tid;
            const int r = u >> 3, g = u & 7;
            cp_async16(uS + 0 * ACH + r * PADB + g * 16, As + (size_t)r * DD + g * 8);
        }
#pragma unroll
        for (int i = 0; i < 4; ++i) {
            const int u = i * 256 + tid;
            const int r = u >> 3, g = u & 7;
            cp_async16(uS + 2 * ACH + r * PADB + g * 16, Bs + (size_t)r * DD + g * 8);
        }
        CP_COMMIT();
    }

#pragma unroll
    for (int c = 0; c < 4; ++c) {
        __syncthreads();

        if (c < 3) {
            const int n = c + 1;
            const int nb = n & 1;
            {
                const __half* As = aBase[aSrcT[n]] + (size_t)row0 * DD + aKoT[n];
                const uint32_t dst = uS + nb * ACH;
#pragma unroll
                for (int i = 0; i < 4; ++i) {
                    const int u = i * 256 + tid;
                    const int r = u >> 3, g = u & 7;
                    cp_async16(dst + r * PADB + g * 16, As + (size_t)r * DD + g * 8);
                }
            }
            {
                const __half* Bs = w + (size_t)bSlT[n] * 16384 + bKoT[n];
                const uint32_t dst = uS + 2 * ACH + nb * ACH;
#pragma unroll
                for (int i = 0; i < 4; ++i) {
                    const int u = i * 256 + tid;
                    const int r = u >> 3, g = u & 7;
                    cp_async16(dst + r * PADB + g * 16, Bs + (size_t)r * DD + g * 8);
                }
            }
            CP_COMMIT();
            CP_WAIT1();
        } else {
            CP_WAIT0();
        }
        __syncthreads();

        const int cb = c & 1;
        const uint32_t uA = uS + cb * ACH;
        const uint32_t uB = uS + 2 * ACH + cb * ACH;

#pragma unroll
        for (int ks = 0; ks < 4; ++ks) {
            uint32_t af[4][4];
#pragma unroll
            for (int mt = 0; mt < 4; ++mt) {
                const uint32_t addr = uA + (a_row + mt * 16) * PADB + ks * 32 + a_kb;
                asm volatile("ldmatrix.sync.aligned.m8n8.x4.shared.b16 {%0,%1,%2,%3}, [%4];"
                             : "=r"(af[mt][0]), "=r"(af[mt][1]),
                               "=r"(af[mt][2]), "=r"(af[mt][3])
                             : "r"(addr));
            }
            uint32_t bfr[4][2];
#pragma unroll
            for (int nt = 0; nt < 4; ++nt) {
                const uint32_t addr = uB + (b_row + nt * 8) * PADB + ks * 32 + b_kb;
                asm volatile("ldmatrix.sync.aligned.m8n8.x2.shared.b16 {%0,%1}, [%2];"
                             : "=r"(bfr[nt][0]), "=r"(bfr[nt][1])
                             : "r"(addr));
            }
#pragma unroll
            for (int mt = 0; mt < 4; ++mt)
#pragma unroll
                for (int nt = 0; nt < 4; ++nt) {
                    asm volatile(
                        "mma.sync.aligned.m16n8k16.row.col.f32.f16.f16.f32 "
                        "{%0,%1,%2,%3}, {%4,%5,%6,%7}, {%8,%9}, {%0,%1,%2,%3};"
                        : "+f"(acc[mt][nt][0]), "+f"(acc[mt][nt][1]),
                          "+f"(acc[mt][nt][2]), "+f"(acc[mt][nt][3])
                        : "r"(af[mt][0]), "r"(af[mt][1]),
                          "r"(af[mt][2]), "r"(af[mt][3]),
                          "r"(bfr[nt][0]), "r"(bfr[nt][1]));
                }
        }
    }

    // ---- epilogue ----
    const int col_base = wn * 32 + ((lane & 3) << 1);
    float bv[4][2];
#pragma unroll
    for (int nt = 0; nt < 4; ++nt) {
        bv[nt][0] = __ldg(bias + col_base + nt * 8);
        bv[nt][1] = __ldg(bias + col_base + nt * 8 + 1);
    }

#pragma unroll
    for (int mt = 0; mt < 4; ++mt) {
        const int r0 = row0 + wm * 64 + mt * 16 + (lane >> 2);
        const int r1 = r0 + 8;
#pragma unroll
        for (int nt = 0; nt < 4; ++nt) {
            const int col = col_base + nt * 8;
            float v0 = acc[mt][nt][0] + bv[nt][0];
            float v1 = acc[mt][nt][1] + bv[nt][1];
            float v2 = acc[mt][nt][2] + bv[nt][0];
            float v3 = acc[mt][nt][3] + bv[nt][1];
            if (relu_split) {
                v0 = fmaxf(v0, 0.f); v1 = fmaxf(v1, 0.f);
                v2 = fmaxf(v2, 0.f); v3 = fmaxf(v3, 0.f);
                if (r0 < NN)
                    *(__half2*)(of16 + (size_t)r0 * DD + col) = __floats2half2_rn(v0, v1);
                if (r1 < NN)
                    *(__half2*)(of16 + (size_t)r1 * DD + col) = __floats2half2_rn(v2, v3);
            } else {
                if (r0 < NN) *(float2*)(outf + (size_t)r0 * DD + col) = make_float2(v0, v1);
                if (r1 < NN) *(float2*)(outf + (size_t)r1 * DD + col) = make_float2(v2, v3);
            }
        }
    }
}

// ---------------------------------------------------------------------------
// Launch sequence (default stream, graph-capturable, allocation-free)
// ---------------------------------------------------------------------------
extern "C" void kernel_launch(void* const* d_in, const int* in_sizes, int n_in,
                              void* d_out, int out_size)
{
    const float* x   = (const float*)d_in[0];
    const void*  ei  = d_in[1];
    const float* W1l = (const float*)d_in[2];
    const float* b1  = (const float*)d_in[3];
    const float* W1r = (const float*)d_in[4];
    const float* W2l = (const float*)d_in[5];
    const float* b2  = (const float*)d_in[6];
    const float* W2r = (const float*)d_in[7];
    float* out = (float*)d_out;

    __half *xf, *hf, *aggf, *wpack;
    int *srcs, *rp, *pos, *cnt, *bs;
    cudaGetSymbolAddress((void**)&xf,    g_xf);
    cudaGetSymbolAddress((void**)&hf,    g_hf);
    cudaGetSymbolAddress((void**)&aggf,  g_aggf);
    cudaGetSymbolAddress((void**)&wpack, g_wpack);
    cudaGetSymbolAddress((void**)&srcs,  g_srcs);
    cudaGetSymbolAddress((void**)&rp,    g_rp);
    cudaGetSymbolAddress((void**)&pos,   g_pos);
    cudaGetSymbolAddress((void**)&cnt,   g_cnt);
    cudaGetSymbolAddress((void**)&bs,    g_bs);

    cudaFuncSetAttribute(node_mma_kernel,
                         cudaFuncAttributeMaxDynamicSharedMemorySize, NODE_SMEM);

    detect_kernel<<<1, 256>>>((const unsigned int*)ei);

    // CSR build
    zero_int_kernel<<<64, 256>>>((int4*)cnt, NN / 4);
    hist_kernel<<<2048, 256>>>(ei, cnt);
    scan1_kernel<<<NB_SCAN, 256>>>(cnt, rp, bs);
    scan2_kernel<<<1, 128>>>(bs);
    scan3_kernel<<<(NN + 255) / 256, 256>>>(rp, pos, bs);
    fill_kernel<<<2048, 256>>>(ei, pos, srcs);

    // fp16 conversions / weight packing
    convert_x_kernel<<<(NN * 32 + 255) / 256, 256>>>((const float4*)x, xf);
    prep_w_kernel<<<32, 256>>>(W1l, W1r, W2l, W2r, (__half*)wpack);

    // Layer 1
    gather_f16_kernel<<<(NN * 32 + 255) / 256, 256>>>(xf, rp, srcs, aggf);
    node_mma_kernel<<<NTILE, 256, NODE_SMEM>>>(aggf, xf, wpack, b1,
                                               nullptr, hf, 1);

    // Layer 2
    gather_f16_kernel<<<(NN * 32 + 255) / 256, 256>>>(hf, rp, srcs, aggf);
    node_mma_kernel<<<NTILE, 256, NODE_SMEM>>>(aggf, hf, wpack + 2 * 16384, b2,
                                               out, nullptr, 0);
}

// round 13
// speedup vs baseline: 3.6271x; 1.0298x over previous
#include <cuda_runtime.h>
#include <cuda_fp16.h>
#include <cstdint>
#include <cstddef>

#define NN 100000
#define NE 1600000
#define DD 128
#define NPAD 100096          // 782 * 128
#define NTILE 782
#define NB_SCAN 98           // ceil(100000 / 1024)

// combo kernel grid sections
#define CB_CONV  12500       // convert_x blocks
#define CB_ZERO  98          // zero cnt blocks
#define CB_PREP  32          // prep_w blocks
#define CB_TOTAL (CB_CONV + CB_ZERO + CB_PREP + 1)  // +1 detect

// ---------------------------------------------------------------------------
// Device scratch (no allocation allowed)
// ---------------------------------------------------------------------------
__device__ __align__(16) __half g_xf[(size_t)NPAD * DD];    // x as fp16
__device__ __align__(16) __half g_hf[(size_t)NPAD * DD];    // h as fp16
__device__ __align__(16) __half g_aggf[(size_t)NPAD * DD];  // aggregated mean fp16
__device__ __align__(16) __half g_wpack[4 * 128 * 128];     // Wl1,Wr1,Wl2,Wr2 fp16
__device__ int g_srcs[NE];
__device__ int g_rp[NN + 1];
__device__ int g_pos[NN];
__device__ int g_cnt[NN];
__device__ int g_bs[128];
__device__ int g_is64;

// ---------------------------------------------------------------------------
// helpers
// ---------------------------------------------------------------------------
__device__ __forceinline__ uint32_t smem_to_u32(const void* p) {
    uint32_t a;
    asm("{ .reg .u64 t; cvta.to.shared.u64 t, %1; cvt.u32.u64 %0, t; }"
        : "=r"(a) : "l"(p));
    return a;
}
__device__ __forceinline__ void cp_async16(uint32_t saddr, const void* gptr) {
    asm volatile("cp.async.cg.shared.global [%0], [%1], 16;"
                 :: "r"(saddr), "l"(gptr));
}
#define CP_COMMIT() asm volatile("cp.async.commit_group;" ::: "memory")
#define CP_WAIT1()  asm volatile("cp.async.wait_group 1;" ::: "memory")
#define CP_WAIT0()  asm volatile("cp.async.wait_group 0;" ::: "memory")

// ---------------------------------------------------------------------------
// Combo kernel: [convert_x | zero cnt | prep_w | detect] by grid section.
// All sections independent; later kernels depend on all of them.
// ---------------------------------------------------------------------------
__global__ void combo_kernel(const float4* __restrict__ x,
                             const unsigned int* __restrict__ ebuf,
                             const float* __restrict__ Wl1, const float* __restrict__ Wr1,
                             const float* __restrict__ Wl2, const float* __restrict__ Wr2,
                             __half* __restrict__ xf,
                             __half* __restrict__ wpack,
                             int* __restrict__ cnt) {
    const int b = blockIdx.x;
    const int t = threadIdx.x;

    if (b < CB_CONV) {
        // ---- convert x -> fp16 ----
        const int id = b * 256 + t;
        const int row = id >> 5, lane = id & 31;
        if (row >= NN) return;
        float4 v = x[(size_t)row * 32 + lane];
        __half2 f0 = __floats2half2_rn(v.x, v.y);
        __half2 f1 = __floats2half2_rn(v.z, v.w);
        *(uint2*)(xf + (size_t)row * DD + lane * 4) =
            make_uint2(*(unsigned*)&f0, *(unsigned*)&f1);
    } else if (b < CB_CONV + CB_ZERO) {
        // ---- zero cnt ----
        const int i = (b - CB_CONV) * 256 + t;
        if (i < NN / 4) ((int4*)cnt)[i] = make_int4(0, 0, 0, 0);
    } else if (b < CB_CONV + CB_ZERO + CB_PREP) {
        // ---- weight pack fp32 -> fp16 ----
        const int id = (b - CB_CONV - CB_ZERO) * 256 + t;   // 0..8191
        const int tIdx = id >> 11;
        const int rem = id & 2047;
        const int j = rem >> 4, cu = rem & 15;
        const float* W = (tIdx == 0) ? Wl1 : (tIdx == 1) ? Wr1 : (tIdx == 2) ? Wl2 : Wr2;
        const float4* p = (const float4*)(W + (size_t)j * DD + cu * 8);
        float4 v0 = p[0], v1 = p[1];
        __half2 h0 = __floats2half2_rn(v0.x, v0.y);
        __half2 h1 = __floats2half2_rn(v0.z, v0.w);
        __half2 h2 = __floats2half2_rn(v1.x, v1.y);
        __half2 h3 = __floats2half2_rn(v1.z, v1.w);
        __half* dst = wpack + (size_t)tIdx * 16384 + (size_t)j * DD + cu * 8;
        *(uint4*)dst = make_uint4(*(unsigned*)&h0, *(unsigned*)&h1,
                                  *(unsigned*)&h2, *(unsigned*)&h3);
    } else {
        // ---- int64/int32 detection ----
        __shared__ int nz;
        if (t == 0) nz = 0;
        __syncthreads();
        for (int i = t; i < 8192; i += 256)
            if (ebuf[2 * i + 1] != 0u) nz = 1;
        __syncthreads();
        if (t == 0) g_is64 = (nz == 0) ? 1 : 0;
    }
}

// ---------------------------------------------------------------------------
// hist: 2 edges per thread via 16B loads
// ---------------------------------------------------------------------------
__global__ void hist_kernel(const void* __restrict__ edges, int* __restrict__ cnt) {
    const int is64 = g_is64;
    int i2 = blockIdx.x * blockDim.x + threadIdx.x;          // edge-pair index
    const int stride = gridDim.x * blockDim.x;
    if (is64) {
        const longlong2* d = (const longlong2*)((const long long*)edges + NE);
        for (; i2 < NE / 2; i2 += stride) {
            longlong2 v = __ldg(&d[i2]);
            atomicAdd(&cnt[(int)v.x], 1);
            atomicAdd(&cnt[(int)v.y], 1);
        }
    } else {
        const int2* d = (const int2*)((const int*)edges + NE);
        for (; i2 < NE / 2; i2 += stride) {
            int2 v = __ldg(&d[i2]);
            atomicAdd(&cnt[v.x], 1);
            atomicAdd(&cnt[v.y], 1);
        }
    }
}

// ---------------------------------------------------------------------------
// scan1: per-1024-block exclusive scan, emits block sums
// ---------------------------------------------------------------------------
__global__ void scan1_kernel(const int* __restrict__ cnt, int* __restrict__ rp,
                             int* __restrict__ bs) {
    __shared__ int wsum[8];
    const int t = threadIdx.x, lane = t & 31, w = t >> 5;
    const int base = blockIdx.x * 1024 + t * 4;
    int v0 = (base + 0 < NN) ? cnt[base + 0] : 0;
    int v1 = (base + 1 < NN) ? cnt[base + 1] : 0;
    int v2 = (base + 2 < NN) ? cnt[base + 2] : 0;
    int v3 = (base + 3 < NN) ? cnt[base + 3] : 0;
    const int tot = v0 + v1 + v2 + v3;
    int inc = tot;
#pragma unroll
    for (int off = 1; off < 32; off <<= 1) {
        int n = __shfl_up_sync(0xffffffff, inc, off);
        if (lane >= off) inc += n;
    }
    if (lane == 31) wsum[w] = inc;
    __syncthreads();
    if (w == 0) {
        int s = (lane < 8) ? wsum[lane] : 0;
#pragma unroll
        for (int off = 1; off < 8; off <<= 1) {
            int n = __shfl_up_sync(0xffffffff, s, off);
            if (lane >= off) s += n;
        }
        if (lane < 8) wsum[lane] = s;
    }
    __syncthreads();
    const int wbase = (w > 0) ? wsum[w - 1] : 0;
    const int exc = wbase + inc - tot;
    if (base + 0 < NN) rp[base + 0] = exc;
    if (base + 1 < NN) rp[base + 1] = exc + v0;
    if (base + 2 < NN) rp[base + 2] = exc + v0 + v1;
    if (base + 3 < NN) rp[base + 3] = exc + v0 + v1 + v2;
    if (t == 255) bs[blockIdx.x] = wbase + inc;
}

// ---------------------------------------------------------------------------
// scan23: each block redundantly scans the 98 block sums, then applies.
// ---------------------------------------------------------------------------
__global__ void scan23_kernel(int* __restrict__ rp, int* __restrict__ pos,
                              const int* __restrict__ bs) {
    __shared__ int sbs[NB_SCAN];
    const int t = threadIdx.x;
    if (t < NB_SCAN) sbs[t] = bs[t];
    __syncthreads();
    const int i = blockIdx.x * blockDim.x + t;
    if (i < NN) {
        const int k = i >> 10;
        int pre = 0;
        for (int j = 0; j < k; ++j) pre += sbs[j];   // k <= 97, smem broadcast
        const int v = rp[i] + pre;
        rp[i] = v;
        pos[i] = v;
    }
    if (i == 0) rp[NN] = NE;
}

// ---------------------------------------------------------------------------
// fill: 2 edges per thread via 16B loads
// ---------------------------------------------------------------------------
__global__ void fill_kernel(const void* __restrict__ edges, int* __restrict__ pos,
                            int* __restrict__ srcs) {
    const int is64 = g_is64;
    int i2 = blockIdx.x * blockDim.x + threadIdx.x;
    const int stride = gridDim.x * blockDim.x;
    if (is64) {
        const longlong2* sp = (const longlong2*)edges;
        const longlong2* dp = (const longlong2*)((const long long*)edges + NE);
        for (; i2 < NE / 2; i2 += stride) {
            longlong2 s = __ldg(&sp[i2]);
            longlong2 d = __ldg(&dp[i2]);
            srcs[atomicAdd(&pos[(int)d.x], 1)] = (int)s.x;
            srcs[atomicAdd(&pos[(int)d.y], 1)] = (int)s.y;
        }
    } else {
        const int2* sp = (const int2*)edges;
        const int2* dp = (const int2*)((const int*)edges + NE);
        for (; i2 < NE / 2; i2 += stride) {
            int2 s = __ldg(&sp[i2]);
            int2 d = __ldg(&dp[i2]);
            srcs[atomicAdd(&pos[d.x], 1)] = s.x;
            srcs[atomicAdd(&pos[d.y], 1)] = s.y;
        }
    }
}

// ---------------------------------------------------------------------------
// Gather: warp per dst node. Lane-parallel index fetch (covers deg<=32 in one
// coalesced load) + shfl distribution + unroll-4 feature loads for MLP.
// fp32 accumulate -> fp16 mean out.
// ---------------------------------------------------------------------------
__global__ void gather_f16_kernel(const __half* __restrict__ xin,
                                  const int* __restrict__ rp,
                                  const int* __restrict__ srcs,
                                  __half* __restrict__ aggf) {
    const int warp = (blockIdx.x * blockDim.x + threadIdx.x) >> 5;
    const int lane = threadIdx.x & 31;
    if (warp >= NN) return;
    const int s = rp[warp], e = rp[warp + 1];
    const int deg = e - s;
    float4 acc = make_float4(0.f, 0.f, 0.f, 0.f);

    // lane-parallel index fetch for first 32 neighbors
    const int myidx = (s + lane < e) ? srcs[s + lane] : 0;
    const int n = (deg < 32) ? deg : 32;

#pragma unroll 4
    for (int i = 0; i < n; ++i) {
        const int sidx = __shfl_sync(0xffffffff, myidx, i);
        const uint2 u = __ldg((const uint2*)(xin + (size_t)sidx * DD + lane * 4));
        float2 a0 = __half22float2(*(const __half2*)&u.x);
        float2 a1 = __half22float2(*(const __half2*)&u.y);
        acc.x += a0.x; acc.y += a0.y; acc.z += a1.x; acc.w += a1.y;
    }
    // rare tail (deg > 32)
    for (int i = s + 32; i < e; ++i) {
        const int sidx = srcs[i];
        const uint2 u = __ldg((const uint2*)(xin + (size_t)sidx * DD + lane * 4));
        float2 a0 = __half22float2(*(const __half2*)&u.x);
        float2 a1 = __half22float2(*(const __half2*)&u.y);
        acc.x += a0.x; acc.y += a0.y; acc.z += a1.x; acc.w += a1.y;
    }

    const float inv = 1.0f / fmaxf((float)deg, 1.0f);
    __half2 o0 = __floats2half2_rn(acc.x * inv, acc.y * inv);
    __half2 o1 = __floats2half2_rn(acc.z * inv, acc.w * inv);
    *(uint2*)(aggf + (size_t)warp * DD + lane * 4) =
        make_uint2(*(unsigned*)&o0, *(unsigned*)&o1);
}

// ---------------------------------------------------------------------------
// fp16 mma.sync node GEMM, cp.async double-buffered.
// out = [agg|x] @ [Wl;Wr]^T + bias ; 4 chunks of K=64 (single term).
// CTA: 128x128 C; 8 warps 2x4, each 64x32; SMEM rows padded to 144B.
// ---------------------------------------------------------------------------
#define PADB 144
#define ACH  (128 * PADB)          // 18432 bytes per buffer
#define NODE_SMEM (4 * ACH)        // 73728

__global__ void __launch_bounds__(256, 2)
node_mma_kernel(const __half* __restrict__ aggf,
                const __half* __restrict__ xf,    // x or h
                const __half* __restrict__ w,     // layer slots: +0 Wl, +16384 Wr
                const float* __restrict__ bias,
                float* __restrict__ outf,
                __half* __restrict__ of16,
                int relu_split)
{
    extern __shared__ char smem[];
    const uint32_t uS = smem_to_u32(smem);

    const int tid  = threadIdx.x;
    const int wid  = tid >> 5;
    const int lane = tid & 31;
    const int wm   = wid >> 2;          // 0..1
    const int wn   = wid & 3;           // 0..3
    const int row0 = blockIdx.x << 7;

    // 4 chunks: {agg,k0},{agg,k64},{x,k0},{x,k64} ; B: Wl/Wl/Wr/Wr
    const int aSrcT[4] = {0, 0, 1, 1};
    const int aKoT [4] = {0, 64, 0, 64};
    const int bSlT [4] = {0, 0, 1, 1};
    const int bKoT [4] = {0, 64, 0, 64};
    const __half* aBase[2] = {aggf, xf};

    const int a_row = wm * 64 + (lane & 15);
    const int a_kb  = ((lane >> 4) & 1) << 4;
    const int b_row = wn * 32 + (lane & 7);
    const int b_kb  = ((lane >> 3) & 1) << 4;

    float acc[4][4][4];
#pragma unroll
    for (int mt = 0; mt < 4; ++mt)
#pragma unroll
        for (int nt = 0; nt < 4; ++nt)
#pragma unroll
            for (int q = 0; q < 4; ++q) acc[mt][nt][q] = 0.f;

    // ---- issue chunk-0 loads ----
    {
        const __half* As = aBase[0] + (size_t)row0 * DD;
        const __half* Bs = w;
#pragma unroll
        for (int i = 0; i < 4; ++i) {
            const int u = i * 256 + tid;
            const int r = u >> 3, g = u & 7;
            cp_async16(uS + 0 * ACH + r * PADB + g * 16, As + (size_t)r * DD + g * 8);
        }
#pragma unroll
        for (int i = 0; i < 4; ++i) {
            const int u = i * 256 + tid;
            const int r = u >> 3, g = u & 7;
            cp_async16(uS + 2 * ACH + r * PADB + g * 16, Bs + (size_t)r * DD + g * 8);
        }
        CP_COMMIT();
    }

#pragma unroll
    for (int c = 0; c < 4; ++c) {
        __syncthreads();

        if (c < 3) {
            const int n = c + 1;
            const int nb = n & 1;
            {
                const __half* As = aBase[aSrcT[n]] + (size_t)row0 * DD + aKoT[n];
                const uint32_t dst = uS + nb * ACH;
#pragma unroll
                for (int i = 0; i < 4; ++i) {
                    const int u = i * 256 + tid;
                    const int r = u >> 3, g = u & 7;
                    cp_async16(dst + r * PADB + g * 16, As + (size_t)r * DD + g * 8);
                }
            }
            {
                const __half* Bs = w + (size_t)bSlT[n] * 16384 + bKoT[n];
                const uint32_t dst = uS + 2 * ACH + nb * ACH;
#pragma unroll
                for (int i = 0; i < 4; ++i) {
                    const int u = i * 256 + tid;
                    const int r = u >> 3, g = u & 7;
                    cp_async16(dst + r * PADB + g * 16, Bs + (size_t)r * DD + g * 8);
                }
            }
            CP_COMMIT();
            CP_WAIT1();
        } else {
            CP_WAIT0();
        }
        __syncthreads();

        const int cb = c & 1;
        const uint32_t uA = uS + cb * ACH;
        const uint32_t uB = uS + 2 * ACH + cb * ACH;

#pragma unroll
        for (int ks = 0; ks < 4; ++ks) {
            uint32_t af[4][4];
#pragma unroll
            for (int mt = 0; mt < 4; ++mt) {
                const uint32_t addr = uA + (a_row + mt * 16) * PADB + ks * 32 + a_kb;
                asm volatile("ldmatrix.sync.aligned.m8n8.x4.shared.b16 {%0,%1,%2,%3}, [%4];"
                             : "=r"(af[mt][0]), "=r"(af[mt][1]),
                               "=r"(af[mt][2]), "=r"(af[mt][3])
                             : "r"(addr));
            }
            uint32_t bfr[4][2];
#pragma unroll
            for (int nt = 0; nt < 4; ++nt) {
                const uint32_t addr = uB + (b_row + nt * 8) * PADB + ks * 32 + b_kb;
                asm volatile("ldmatrix.sync.aligned.m8n8.x2.shared.b16 {%0,%1}, [%2];"
                             : "=r"(bfr[nt][0]), "=r"(bfr[nt][1])
                             : "r"(addr));
            }
#pragma unroll
            for (int mt = 0; mt < 4; ++mt)
#pragma unroll
                for (int nt = 0; nt < 4; ++nt) {
                    asm volatile(
                        "mma.sync.aligned.m16n8k16.row.col.f32.f16.f16.f32 "
                        "{%0,%1,%2,%3}, {%4,%5,%6,%7}, {%8,%9}, {%0,%1,%2,%3};"
                        : "+f"(acc[mt][nt][0]), "+f"(acc[mt][nt][1]),
                          "+f"(acc[mt][nt][2]), "+f"(acc[mt][nt][3])
                        : "r"(af[mt][0]), "r"(af[mt][1]),
                          "r"(af[mt][2]), "r"(af[mt][3]),
                          "r"(bfr[nt][0]), "r"(bfr[nt][1]));
                }
        }
    }

    // ---- epilogue ----
    const int col_base = wn * 32 + ((lane & 3) << 1);
    float bv[4][2];
#pragma unroll
    for (int nt = 0; nt < 4; ++nt) {
        bv[nt][0] = __ldg(bias + col_base + nt * 8);
        bv[nt][1] = __ldg(bias + col_base + nt * 8 + 1);
    }

#pragma unroll
    for (int mt = 0; mt < 4; ++mt) {
        const int r0 = row0 + wm * 64 + mt * 16 + (lane >> 2);
        const int r1 = r0 + 8;
#pragma unroll
        for (int nt = 0; nt < 4; ++nt) {
            const int col = col_base + nt * 8;
            float v0 = acc[mt][nt][0] + bv[nt][0];
            float v1 = acc[mt][nt][1] + bv[nt][1];
            float v2 = acc[mt][nt][2] + bv[nt][0];
            float v3 = acc[mt][nt][3] + bv[nt][1];
            if (relu_split) {
                v0 = fmaxf(v0, 0.f); v1 = fmaxf(v1, 0.f);
                v2 = fmaxf(v2, 0.f); v3 = fmaxf(v3, 0.f);
                if (r0 < NN)
                    *(__half2*)(of16 + (size_t)r0 * DD + col) = __floats2half2_rn(v0, v1);
                if (r1 < NN)
                    *(__half2*)(of16 + (size_t)r1 * DD + col) = __floats2half2_rn(v2, v3);
            } else {
                if (r0 < NN) *(float2*)(outf + (size_t)r0 * DD + col) = make_float2(v0, v1);
                if (r1 < NN) *(float2*)(outf + (size_t)r1 * DD + col) = make_float2(v2, v3);
            }
        }
    }
}

// ---------------------------------------------------------------------------
// Launch sequence (default stream, graph-capturable, allocation-free)
// 9 kernels total.
// ---------------------------------------------------------------------------
extern "C" void kernel_launch(void* const* d_in, const int* in_sizes, int n_in,
                              void* d_out, int out_size)
{
    const float* x   = (const float*)d_in[0];
    const void*  ei  = d_in[1];
    const float* W1l = (const float*)d_in[2];
    const float* b1  = (const float*)d_in[3];
    const float* W1r = (const float*)d_in[4];
    const float* W2l = (const float*)d_in[5];
    const float* b2  = (const float*)d_in[6];
    const float* W2r = (const float*)d_in[7];
    float* out = (float*)d_out;

    __half *xf, *hf, *aggf, *wpack;
    int *srcs, *rp, *pos, *cnt, *bs;
    cudaGetSymbolAddress((void**)&xf,    g_xf);
    cudaGetSymbolAddress((void**)&hf,    g_hf);
    cudaGetSymbolAddress((void**)&aggf,  g_aggf);
    cudaGetSymbolAddress((void**)&wpack, g_wpack);
    cudaGetSymbolAddress((void**)&srcs,  g_srcs);
    cudaGetSymbolAddress((void**)&rp,    g_rp);
    cudaGetSymbolAddress((void**)&pos,   g_pos);
    cudaGetSymbolAddress((void**)&cnt,   g_cnt);
    cudaGetSymbolAddress((void**)&bs,    g_bs);

    cudaFuncSetAttribute(node_mma_kernel,
                         cudaFuncAttributeMaxDynamicSharedMemorySize, NODE_SMEM);

    // combo: convert_x | zero cnt | prep_w | detect
    combo_kernel<<<CB_TOTAL, 256>>>((const float4*)x, (const unsigned int*)ei,
                                    W1l, W1r, W2l, W2r, xf, wpack, cnt);

    // CSR build
    hist_kernel<<<1600, 256>>>(ei, cnt);
    scan1_kernel<<<NB_SCAN, 256>>>(cnt, rp, bs);
    scan23_kernel<<<(NN + 255) / 256, 256>>>(rp, pos, bs);
    fill_kernel<<<1600, 256>>>(ei, pos, srcs);

    // Layer 1
    gather_f16_kernel<<<(NN * 32 + 255) / 256, 256>>>(xf, rp, srcs, aggf);
    node_mma_kernel<<<NTILE, 256, NODE_SMEM>>>(aggf, xf, wpack, b1,
                                               nullptr, hf, 1);

    // Layer 2
    gather_f16_kernel<<<(NN * 32 + 255) / 256, 256>>>(hf, rp, srcs, aggf);
    node_mma_kernel<<<NTILE, 256, NODE_SMEM>>>(aggf, hf, wpack + 2 * 16384, b2,
                                               out, nullptr, 0);
}